// round 1
// baseline (speedup 1.0000x reference)
#include <cuda_runtime.h>
#include <math.h>
#include <stdint.h>

#define TSEQ   2048
#define DMODEL 2048
#define NH     16
#define DHEAD  128
#define DROPE  64
#define DCONT  64
#define SCALE_ATT 0.08838834764831845f  /* 1/sqrt(128) */

/* ------------------------------------------------------------------ */
/* Scratch (device globals: no allocation allowed in kernel_launch)   */
/* ------------------------------------------------------------------ */
__device__ float g_qd[TSEQ * 512];     /* x @ Wq_down            */
__device__ float g_qc[TSEQ * 1024];    /* q_down @ Wq_up         */
__device__ float g_qr[TSEQ * 1024];    /* x @ Wq_rope            */
__device__ float g_kv[TSEQ * 512];     /* x @ Wkv_down           */
__device__ float g_kc[TSEQ * 1024];    /* kv @ Wk_up             */
__device__ float g_kr[TSEQ * 1024];    /* x @ Wk_rope            */
__device__ float g_vu[TSEQ * 2048];    /* kv @ Wv_up             */
__device__ float g_Q[NH * TSEQ * DHEAD];
__device__ float g_K[NH * TSEQ * DHEAD];
__device__ float g_V[NH * TSEQ * DHEAD];
__device__ float g_O[TSEQ * 2048];     /* attention out [t, h*128+d] */

/* ------------------------------------------------------------------ */
/* Tiled fp32 GEMM: C[M,N] = A[M,K] @ B[K,N].  BM=BN=64, BK=16.       */
/* 256 threads, 4x4 micro-tile per thread. All dims multiples of 64/16*/
/* ------------------------------------------------------------------ */
__global__ void __launch_bounds__(256) gemm64x64(
    const float* __restrict__ A, const float* __restrict__ B,
    float* __restrict__ C, int M, int N, int K)
{
    __shared__ float As[16][68];   /* A tile transposed [k][m], pad 68 */
    __shared__ float Bs[16][64];   /* B tile [k][n]                    */

    const int tid = threadIdx.x;
    const int tx  = tid & 15;
    const int ty  = tid >> 4;
    const int bm  = blockIdx.y << 6;
    const int bn  = blockIdx.x << 6;

    /* load-index precompute */
    const int lm  = tid >> 2;          /* A row within tile 0..63  */
    const int lk  = (tid & 3) << 2;    /* A k offset 0,4,8,12      */
    const int bk  = tid >> 4;          /* B k row 0..15            */
    const int bn4 = (tid & 15) << 2;   /* B n offset               */

    float acc[4][4] = {};

    for (int k0 = 0; k0 < K; k0 += 16) {
        float4 a4 = *(const float4*)(A + (size_t)(bm + lm) * K + k0 + lk);
        float4 b4 = *(const float4*)(B + (size_t)(k0 + bk) * N + bn + bn4);
        As[lk + 0][lm] = a4.x;
        As[lk + 1][lm] = a4.y;
        As[lk + 2][lm] = a4.z;
        As[lk + 3][lm] = a4.w;
        *(float4*)(&Bs[bk][bn4]) = b4;
        __syncthreads();

#pragma unroll
        for (int k = 0; k < 16; k++) {
            float av[4], bv[4];
            *(float4*)av = *(const float4*)(&As[k][ty << 2]);
            *(float4*)bv = *(const float4*)(&Bs[k][tx << 2]);
#pragma unroll
            for (int i = 0; i < 4; i++)
#pragma unroll
                for (int j = 0; j < 4; j++)
                    acc[i][j] += av[i] * bv[j];
        }
        __syncthreads();
    }

#pragma unroll
    for (int i = 0; i < 4; i++) {
        *(float4*)(C + (size_t)(bm + (ty << 2) + i) * N + bn + (tx << 2)) =
            *(float4*)acc[i];
    }
}

/* ------------------------------------------------------------------ */
/* Pack + RoPE: builds Q/K/V in [h][t][d] layout.                     */
/* grid (TSEQ, NH), 128 threads (one per head-dim).                   */
/* ------------------------------------------------------------------ */
__global__ void __launch_bounds__(128) pack_kernel()
{
    const int t = blockIdx.x;
    const int h = blockIdx.y;
    const int d = threadIdx.x;
    const size_t oidx = ((size_t)h * TSEQ + t) * DHEAD + d;

    /* V copy */
    g_V[oidx] = g_vu[(size_t)t * 2048 + h * DHEAD + d];

    float qv, kvv;
    if (d < DCONT) {
        qv  = g_qc[(size_t)t * 1024 + h * DCONT + d];
        kvv = g_kc[(size_t)t * 1024 + h * DCONT + d];
    } else {
        const int i  = d - DCONT;            /* 0..63 within rope dims */
        const int ip = (i < 32) ? i : i - 32;
        const double inv = pow(10000.0, -(double)ip / 32.0);
        double sd, cd;
        sincos((double)t * inv, &sd, &cd);
        const float c = (float)cd, s = (float)sd;
        const size_t rbase = (size_t)t * 1024 + h * DROPE;
        const float q1 = g_qr[rbase + ip];
        const float q2 = g_qr[rbase + 32 + ip];
        const float k1 = g_kr[rbase + ip];
        const float k2 = g_kr[rbase + 32 + ip];
        if (i < 32) { qv = q1 * c - q2 * s;  kvv = k1 * c - k2 * s; }
        else        { qv = q1 * s + q2 * c;  kvv = k1 * s + k2 * c; }
    }
    g_Q[oidx] = qv;
    g_K[oidx] = kvv;
}

/* ------------------------------------------------------------------ */
/* Causal flash attention, fp32.                                      */
/* grid (TSEQ/16, NH), 128 threads (4 warps).                         */
/* Each warp owns 4 consecutive query rows; lane = key within 32-tile.*/
/* ------------------------------------------------------------------ */
__global__ void __launch_bounds__(128) attn_kernel()
{
    __shared__ float kT[128 * 36];    /* K tile transposed [d][key], pad 36 */
    __shared__ float vs[32 * 128];    /* V tile [key][d]                    */
    __shared__ float qsT[128 * 16];   /* 16 q rows transposed [d][row]      */
    __shared__ float psh[4 * 128];    /* per-warp probs [row-of-4 x key]    */

    const int h     = blockIdx.y;
    const int warp  = threadIdx.x >> 5;
    const int lane  = threadIdx.x & 31;
    const int q0blk = blockIdx.x << 4;

    const float* Kb = g_K + (size_t)h * TSEQ * DHEAD;
    const float* Vb = g_V + (size_t)h * TSEQ * DHEAD;
    const float* Qb = g_Q + (size_t)h * TSEQ * DHEAD;

    /* stage 16 q rows transposed into smem */
    {
        const int r  = threadIdx.x & 15;
        const int d4 = (threadIdx.x >> 4) << 2;   /* 0,4,...,28 */
        for (int dd = d4; dd < 128; dd += 32) {
            float4 q4 = *(const float4*)(Qb + (size_t)(q0blk + r) * DHEAD + dd);
            qsT[(dd + 0) * 16 + r] = q4.x;
            qsT[(dd + 1) * 16 + r] = q4.y;
            qsT[(dd + 2) * 16 + r] = q4.z;
            qsT[(dd + 3) * 16 + r] = q4.w;
        }
    }

    float  m[4], l[4];
    float4 acc[4];
#pragma unroll
    for (int r = 0; r < 4; r++) {
        m[r] = -1e30f; l[r] = 0.f;
        acc[r] = make_float4(0.f, 0.f, 0.f, 0.f);
    }

    const int qbase  = q0blk + (warp << 2);
    const int ntiles = (q0blk + 15) / 32 + 1;

    for (int tile = 0; tile < ntiles; tile++) {
        const int kb = tile << 5;
        __syncthreads();
        /* cooperative load: K transposed + V straight */
#pragma unroll
        for (int kk = warp; kk < 32; kk += 4) {
            const int d0 = lane << 2;
            float4 k4 = *(const float4*)(Kb + (size_t)(kb + kk) * DHEAD + d0);
            kT[(d0 + 0) * 36 + kk] = k4.x;
            kT[(d0 + 1) * 36 + kk] = k4.y;
            kT[(d0 + 2) * 36 + kk] = k4.z;
            kT[(d0 + 3) * 36 + kk] = k4.w;
            *(float4*)(&vs[kk * 128 + d0]) =
                *(const float4*)(Vb + (size_t)(kb + kk) * DHEAD + d0);
        }
        __syncthreads();

        /* scores: 4 q rows vs key=lane */
        float s[4] = {0.f, 0.f, 0.f, 0.f};
#pragma unroll 16
        for (int d = 0; d < 128; d++) {
            const float  kv = kT[d * 36 + lane];
            const float4 q4 = *(const float4*)(&qsT[d * 16 + (warp << 2)]);
            s[0] += kv * q4.x;
            s[1] += kv * q4.y;
            s[2] += kv * q4.z;
            s[3] += kv * q4.w;
        }

        const int key = kb + lane;
        float p[4];
#pragma unroll
        for (int r = 0; r < 4; r++) {
            float sv = s[r] * SCALE_ATT;
            if (key > qbase + r) sv = -1e30f;
            float mc = sv;
#pragma unroll
            for (int o = 16; o; o >>= 1)
                mc = fmaxf(mc, __shfl_xor_sync(0xffffffffu, mc, o));
            const float mn    = fmaxf(m[r], mc);
            const float alpha = __expf(m[r] - mn);
            const float pv    = __expf(sv - mn);
            float ps = pv;
#pragma unroll
            for (int o = 16; o; o >>= 1)
                ps += __shfl_xor_sync(0xffffffffu, ps, o);
            l[r] = l[r] * alpha + ps;
            acc[r].x *= alpha; acc[r].y *= alpha;
            acc[r].z *= alpha; acc[r].w *= alpha;
            m[r] = mn;
            p[r] = pv;
        }

        /* P -> smem so PV reads it as a 16B broadcast instead of shuffles */
        *(float4*)(&psh[warp * 128 + (lane << 2)]) =
            make_float4(p[0], p[1], p[2], p[3]);
        __syncwarp();

#pragma unroll 8
        for (int j = 0; j < 32; j++) {
            const float4 pj = *(const float4*)(&psh[warp * 128 + (j << 2)]);
            const float4 v4 = *(const float4*)(&vs[j * 128 + (lane << 2)]);
            acc[0].x += pj.x * v4.x; acc[0].y += pj.x * v4.y;
            acc[0].z += pj.x * v4.z; acc[0].w += pj.x * v4.w;
            acc[1].x += pj.y * v4.x; acc[1].y += pj.y * v4.y;
            acc[1].z += pj.y * v4.z; acc[1].w += pj.y * v4.w;
            acc[2].x += pj.z * v4.x; acc[2].y += pj.z * v4.y;
            acc[2].z += pj.z * v4.z; acc[2].w += pj.z * v4.w;
            acc[3].x += pj.w * v4.x; acc[3].y += pj.w * v4.y;
            acc[3].z += pj.w * v4.z; acc[3].w += pj.w * v4.w;
        }
        __syncwarp();
    }

#pragma unroll
    for (int r = 0; r < 4; r++) {
        const float inv = 1.0f / l[r];
        float4 o4 = make_float4(acc[r].x * inv, acc[r].y * inv,
                                acc[r].z * inv, acc[r].w * inv);
        *(float4*)(&g_O[(size_t)(qbase + r) * DMODEL + h * DHEAD + (lane << 2)]) = o4;
    }
}

/* ------------------------------------------------------------------ */
extern "C" void kernel_launch(void* const* d_in, const int* in_sizes, int n_in,
                              void* d_out, int out_size)
{
    const float* x        = (const float*)d_in[0];
    const float* Wq_down  = (const float*)d_in[1];
    const float* Wq_up    = (const float*)d_in[2];
    const float* Wq_rope  = (const float*)d_in[3];
    const float* Wkv_down = (const float*)d_in[4];
    const float* Wk_up    = (const float*)d_in[5];
    const float* Wv_up    = (const float*)d_in[6];
    const float* Wk_rope  = (const float*)d_in[7];
    const float* Wo       = (const float*)d_in[8];
    float* out = (float*)d_out;

    float *qd, *qc, *qr, *kv, *kc, *kr, *vu, *O;
    cudaGetSymbolAddress((void**)&qd, g_qd);
    cudaGetSymbolAddress((void**)&qc, g_qc);
    cudaGetSymbolAddress((void**)&qr, g_qr);
    cudaGetSymbolAddress((void**)&kv, g_kv);
    cudaGetSymbolAddress((void**)&kc, g_kc);
    cudaGetSymbolAddress((void**)&kr, g_kr);
    cudaGetSymbolAddress((void**)&vu, g_vu);
    cudaGetSymbolAddress((void**)&O,  g_O);

    const dim3 blk(256);

    /* projections */
    gemm64x64<<<dim3( 8, 32), blk>>>(x,  Wq_down,  qd, 2048,  512, 2048);
    gemm64x64<<<dim3(16, 32), blk>>>(qd, Wq_up,    qc, 2048, 1024,  512);
    gemm64x64<<<dim3(16, 32), blk>>>(x,  Wq_rope,  qr, 2048, 1024, 2048);
    gemm64x64<<<dim3( 8, 32), blk>>>(x,  Wkv_down, kv, 2048,  512, 2048);
    gemm64x64<<<dim3(16, 32), blk>>>(kv, Wk_up,    kc, 2048, 1024,  512);
    gemm64x64<<<dim3(16, 32), blk>>>(x,  Wk_rope,  kr, 2048, 1024, 2048);
    gemm64x64<<<dim3(32, 32), blk>>>(kv, Wv_up,    vu, 2048, 2048,  512);

    /* rope + layout */
    pack_kernel<<<dim3(TSEQ, NH), 128>>>();

    /* causal attention */
    attn_kernel<<<dim3(TSEQ / 16, NH), 128>>>();

    /* output projection */
    gemm64x64<<<dim3(32, 32), blk>>>(O, Wo, out, 2048, 2048, 2048);
}

// round 2
// speedup vs baseline: 1.2539x; 1.2539x over previous
#include <cuda_runtime.h>
#include <cuda_bf16.h>
#include <math.h>
#include <stdint.h>

#define TSEQ   2048
#define DMODEL 2048
#define NH     16
#define DHEAD  128
#define DROPE  64
#define DCONT  64
#define SCALE_ATT 0.08838834764831845f  /* 1/sqrt(128) */

/* ------------------------------------------------------------------ */
/* Scratch (device globals: no allocation allowed in kernel_launch)   */
/* ------------------------------------------------------------------ */
__device__ float g_qd[TSEQ * 512];     /* x @ Wq_down            */
__device__ float g_qc[TSEQ * 1024];    /* q_down @ Wq_up         */
__device__ float g_qr[TSEQ * 1024];    /* x @ Wq_rope            */
__device__ float g_kv[TSEQ * 512];     /* x @ Wkv_down           */
__device__ float g_kc[TSEQ * 1024];    /* kv @ Wk_up             */
__device__ float g_kr[TSEQ * 1024];    /* x @ Wk_rope            */
__device__ float g_vu[TSEQ * 2048];    /* kv @ Wv_up             */
__device__ float g_Q[NH * TSEQ * DHEAD];
__device__ float g_K[NH * TSEQ * DHEAD];
__device__ float g_V[NH * TSEQ * DHEAD];
__device__ float g_O[TSEQ * 2048];     /* attention out [t, h*128+d] */

/* ------------------------------------------------------------------ */
/* bf16 split helpers                                                  */
/* ------------------------------------------------------------------ */
__device__ __forceinline__ void split_f4(float4 v, uint2& hi, uint2& lo)
{
    __nv_bfloat16 h0 = __float2bfloat16_rn(v.x);
    __nv_bfloat16 h1 = __float2bfloat16_rn(v.y);
    __nv_bfloat16 h2 = __float2bfloat16_rn(v.z);
    __nv_bfloat16 h3 = __float2bfloat16_rn(v.w);
    __nv_bfloat16 l0 = __float2bfloat16_rn(v.x - __bfloat162float(h0));
    __nv_bfloat16 l1 = __float2bfloat16_rn(v.y - __bfloat162float(h1));
    __nv_bfloat16 l2 = __float2bfloat16_rn(v.z - __bfloat162float(h2));
    __nv_bfloat16 l3 = __float2bfloat16_rn(v.w - __bfloat162float(h3));
    hi.x = (uint32_t)__bfloat16_as_ushort(h0) | ((uint32_t)__bfloat16_as_ushort(h1) << 16);
    hi.y = (uint32_t)__bfloat16_as_ushort(h2) | ((uint32_t)__bfloat16_as_ushort(h3) << 16);
    lo.x = (uint32_t)__bfloat16_as_ushort(l0) | ((uint32_t)__bfloat16_as_ushort(l1) << 16);
    lo.y = (uint32_t)__bfloat16_as_ushort(l2) | ((uint32_t)__bfloat16_as_ushort(l3) << 16);
}

#define LDSM4(r0, r1, r2, r3, addr)                                        \
    asm volatile("ldmatrix.sync.aligned.m8n8.x4.shared.b16 {%0,%1,%2,%3}, [%4];" \
                 : "=r"(r0), "=r"(r1), "=r"(r2), "=r"(r3) : "r"(addr))

#define LDSM4T(r0, r1, r2, r3, addr)                                       \
    asm volatile("ldmatrix.sync.aligned.m8n8.x4.trans.shared.b16 {%0,%1,%2,%3}, [%4];" \
                 : "=r"(r0), "=r"(r1), "=r"(r2), "=r"(r3) : "r"(addr))

#define MMA_BF16(c, a, b0, b1)                                             \
    asm volatile("mma.sync.aligned.m16n8k16.row.col.f32.bf16.bf16.f32 "    \
                 "{%0,%1,%2,%3}, {%4,%5,%6,%7}, {%8,%9}, {%0,%1,%2,%3};"   \
                 : "+f"(c[0]), "+f"(c[1]), "+f"(c[2]), "+f"(c[3])          \
                 : "r"(a[0]), "r"(a[1]), "r"(a[2]), "r"(a[3]),             \
                   "r"(b0), "r"(b1))

/* ------------------------------------------------------------------ */
/* Split-precision bf16 tensor-core GEMM: C = A[M,K] @ B[K,N], fp32   */
/* accuracy via C = Ah*Bh + Ah*Bl + Al*Bh.                            */
/* BM=BN=128, BK=32. 256 threads = 8 warps (4x2), warp tile 32x64.    */
/* M,N multiples of 128; K multiple of 32.                            */
/* ------------------------------------------------------------------ */
__global__ void __launch_bounds__(256) gemm_mma(
    const float* __restrict__ A, const float* __restrict__ B,
    float* __restrict__ C, int M, int N, int K)
{
    __shared__ __nv_bfloat16 Ah[128][40];   /* pitch 40 bf16 = 80B: LDSM conflict-free */
    __shared__ __nv_bfloat16 Al[128][40];
    __shared__ __nv_bfloat16 Bh[32][136];   /* pitch 136 bf16 = 272B: conflict-free    */
    __shared__ __nv_bfloat16 Bl[32][136];

    const int tid  = threadIdx.x;
    const int lane = tid & 31;
    const int warp = tid >> 5;
    const int wm   = (warp >> 1) << 5;   /* warp row base 0..96  */
    const int wn   = (warp & 1) << 6;    /* warp col base 0/64   */
    const int bm   = blockIdx.y << 7;
    const int bn   = blockIdx.x << 7;

    /* global staging indices */
    const int ar = tid >> 3;             /* A row 0..31 per pass  */
    const int ac = (tid & 7) << 2;       /* A col 0..28           */
    const int br = tid >> 5;             /* B row 0..7 per pass   */
    const int bc = (tid & 31) << 2;      /* B col 0..124          */

    /* ldmatrix lane geometry */
    const int arow = lane & 15;
    const int ak   = (lane >> 4) << 3;   /* 0 or 8 */
    const int brow = lane & 15;
    const int bco  = wn + ((lane >> 4) << 3);

    const uint32_t sAh = (uint32_t)__cvta_generic_to_shared(&Ah[0][0]);
    const uint32_t sAl = (uint32_t)__cvta_generic_to_shared(&Al[0][0]);
    const uint32_t sBh = (uint32_t)__cvta_generic_to_shared(&Bh[0][0]);
    const uint32_t sBl = (uint32_t)__cvta_generic_to_shared(&Bl[0][0]);

    float acc[2][8][4];
#pragma unroll
    for (int mt = 0; mt < 2; mt++)
#pragma unroll
        for (int nt = 0; nt < 8; nt++)
#pragma unroll
            for (int i = 0; i < 4; i++) acc[mt][nt][i] = 0.f;

    for (int k0 = 0; k0 < K; k0 += 32) {
        __syncthreads();
        /* stage A tile 128x32 (split fp32 -> hi/lo bf16) */
        const float* Ag = A + (size_t)bm * K + k0;
#pragma unroll
        for (int p = 0; p < 4; p++) {
            float4 v = *(const float4*)(Ag + (size_t)(ar + p * 32) * K + ac);
            uint2 hi, lo; split_f4(v, hi, lo);
            *(uint2*)&Ah[ar + p * 32][ac] = hi;
            *(uint2*)&Al[ar + p * 32][ac] = lo;
        }
        /* stage B tile 32x128 */
        const float* Bg = B + (size_t)k0 * N + bn;
#pragma unroll
        for (int p = 0; p < 4; p++) {
            float4 v = *(const float4*)(Bg + (size_t)(br + p * 8) * N + bc);
            uint2 hi, lo; split_f4(v, hi, lo);
            *(uint2*)&Bh[br + p * 8][bc] = hi;
            *(uint2*)&Bl[br + p * 8][bc] = lo;
        }
        __syncthreads();

#pragma unroll
        for (int ks = 0; ks < 2; ks++) {
            const int kb = ks << 4;
            uint32_t ah[2][4], al_[2][4];
#pragma unroll
            for (int mt = 0; mt < 2; mt++) {
                const uint32_t off =
                    (uint32_t)(((wm + (mt << 4) + arow) * 40 + kb + ak) << 1);
                LDSM4(ah[mt][0], ah[mt][1], ah[mt][2], ah[mt][3], sAh + off);
                LDSM4(al_[mt][0], al_[mt][1], al_[mt][2], al_[mt][3], sAl + off);
            }
            uint32_t bhf[8][2], blf[8][2];
#pragma unroll
            for (int np = 0; np < 4; np++) {
                const uint32_t off =
                    (uint32_t)((((kb + brow) * 136) + bco + (np << 4)) << 1);
                uint32_t r0, r1, r2, r3;
                LDSM4T(r0, r1, r2, r3, sBh + off);
                bhf[2 * np][0] = r0; bhf[2 * np][1] = r1;
                bhf[2 * np + 1][0] = r2; bhf[2 * np + 1][1] = r3;
                LDSM4T(r0, r1, r2, r3, sBl + off);
                blf[2 * np][0] = r0; blf[2 * np][1] = r1;
                blf[2 * np + 1][0] = r2; blf[2 * np + 1][1] = r3;
            }
#pragma unroll
            for (int mt = 0; mt < 2; mt++)
#pragma unroll
                for (int nt = 0; nt < 8; nt++) {
                    MMA_BF16(acc[mt][nt], ah[mt],  bhf[nt][0], bhf[nt][1]);
                    MMA_BF16(acc[mt][nt], ah[mt],  blf[nt][0], blf[nt][1]);
                    MMA_BF16(acc[mt][nt], al_[mt], bhf[nt][0], bhf[nt][1]);
                }
        }
    }

    /* epilogue: D frag (m = lane>>2, n = (lane&3)*2) */
    const int erow = lane >> 2;
    const int ecol = (lane & 3) << 1;
#pragma unroll
    for (int mt = 0; mt < 2; mt++)
#pragma unroll
        for (int nt = 0; nt < 8; nt++) {
            const int r = bm + wm + (mt << 4) + erow;
            const int c = bn + wn + (nt << 3) + ecol;
            *(float2*)(C + (size_t)r * N + c) =
                make_float2(acc[mt][nt][0], acc[mt][nt][1]);
            *(float2*)(C + (size_t)(r + 8) * N + c) =
                make_float2(acc[mt][nt][2], acc[mt][nt][3]);
        }
}

/* ------------------------------------------------------------------ */
/* Pack + RoPE: builds Q/K/V in [h][t][d] layout.                     */
/* ------------------------------------------------------------------ */
__global__ void __launch_bounds__(128) pack_kernel()
{
    const int t = blockIdx.x;
    const int h = blockIdx.y;
    const int d = threadIdx.x;
    const size_t oidx = ((size_t)h * TSEQ + t) * DHEAD + d;

    g_V[oidx] = g_vu[(size_t)t * 2048 + h * DHEAD + d];

    float qv, kvv;
    if (d < DCONT) {
        qv  = g_qc[(size_t)t * 1024 + h * DCONT + d];
        kvv = g_kc[(size_t)t * 1024 + h * DCONT + d];
    } else {
        const int i  = d - DCONT;
        const int ip = (i < 32) ? i : i - 32;
        const double inv = pow(10000.0, -(double)ip / 32.0);
        double sd, cd;
        sincos((double)t * inv, &sd, &cd);
        const float c = (float)cd, s = (float)sd;
        const size_t rbase = (size_t)t * 1024 + h * DROPE;
        const float q1 = g_qr[rbase + ip];
        const float q2 = g_qr[rbase + 32 + ip];
        const float k1 = g_kr[rbase + ip];
        const float k2 = g_kr[rbase + 32 + ip];
        if (i < 32) { qv = q1 * c - q2 * s;  kvv = k1 * c - k2 * s; }
        else        { qv = q1 * s + q2 * c;  kvv = k1 * s + k2 * c; }
    }
    g_Q[oidx] = qv;
    g_K[oidx] = kvv;
}

/* ------------------------------------------------------------------ */
/* Causal flash attention, fp32 (unchanged from R1 — next target).    */
/* ------------------------------------------------------------------ */
__global__ void __launch_bounds__(128) attn_kernel()
{
    __shared__ float kT[128 * 36];
    __shared__ float vs[32 * 128];
    __shared__ float qsT[128 * 16];
    __shared__ float psh[4 * 128];

    const int h     = blockIdx.y;
    const int warp  = threadIdx.x >> 5;
    const int lane  = threadIdx.x & 31;
    const int q0blk = blockIdx.x << 4;

    const float* Kb = g_K + (size_t)h * TSEQ * DHEAD;
    const float* Vb = g_V + (size_t)h * TSEQ * DHEAD;
    const float* Qb = g_Q + (size_t)h * TSEQ * DHEAD;

    {
        const int r  = threadIdx.x & 15;
        const int d4 = (threadIdx.x >> 4) << 2;
        for (int dd = d4; dd < 128; dd += 32) {
            float4 q4 = *(const float4*)(Qb + (size_t)(q0blk + r) * DHEAD + dd);
            qsT[(dd + 0) * 16 + r] = q4.x;
            qsT[(dd + 1) * 16 + r] = q4.y;
            qsT[(dd + 2) * 16 + r] = q4.z;
            qsT[(dd + 3) * 16 + r] = q4.w;
        }
    }

    float  m[4], l[4];
    float4 acc[4];
#pragma unroll
    for (int r = 0; r < 4; r++) {
        m[r] = -1e30f; l[r] = 0.f;
        acc[r] = make_float4(0.f, 0.f, 0.f, 0.f);
    }

    const int qbase  = q0blk + (warp << 2);
    const int ntiles = (q0blk + 15) / 32 + 1;

    for (int tile = 0; tile < ntiles; tile++) {
        const int kb = tile << 5;
        __syncthreads();
#pragma unroll
        for (int kk = warp; kk < 32; kk += 4) {
            const int d0 = lane << 2;
            float4 k4 = *(const float4*)(Kb + (size_t)(kb + kk) * DHEAD + d0);
            kT[(d0 + 0) * 36 + kk] = k4.x;
            kT[(d0 + 1) * 36 + kk] = k4.y;
            kT[(d0 + 2) * 36 + kk] = k4.z;
            kT[(d0 + 3) * 36 + kk] = k4.w;
            *(float4*)(&vs[kk * 128 + d0]) =
                *(const float4*)(Vb + (size_t)(kb + kk) * DHEAD + d0);
        }
        __syncthreads();

        float s[4] = {0.f, 0.f, 0.f, 0.f};
#pragma unroll 16
        for (int d = 0; d < 128; d++) {
            const float  kv = kT[d * 36 + lane];
            const float4 q4 = *(const float4*)(&qsT[d * 16 + (warp << 2)]);
            s[0] += kv * q4.x;
            s[1] += kv * q4.y;
            s[2] += kv * q4.z;
            s[3] += kv * q4.w;
        }

        const int key = kb + lane;
        float p[4];
#pragma unroll
        for (int r = 0; r < 4; r++) {
            float sv = s[r] * SCALE_ATT;
            if (key > qbase + r) sv = -1e30f;
            float mc = sv;
#pragma unroll
            for (int o = 16; o; o >>= 1)
                mc = fmaxf(mc, __shfl_xor_sync(0xffffffffu, mc, o));
            const float mn    = fmaxf(m[r], mc);
            const float alpha = __expf(m[r] - mn);
            const float pv    = __expf(sv - mn);
            float ps = pv;
#pragma unroll
            for (int o = 16; o; o >>= 1)
                ps += __shfl_xor_sync(0xffffffffu, ps, o);
            l[r] = l[r] * alpha + ps;
            acc[r].x *= alpha; acc[r].y *= alpha;
            acc[r].z *= alpha; acc[r].w *= alpha;
            m[r] = mn;
            p[r] = pv;
        }

        *(float4*)(&psh[warp * 128 + (lane << 2)]) =
            make_float4(p[0], p[1], p[2], p[3]);
        __syncwarp();

#pragma unroll 8
        for (int j = 0; j < 32; j++) {
            const float4 pj = *(const float4*)(&psh[warp * 128 + (j << 2)]);
            const float4 v4 = *(const float4*)(&vs[j * 128 + (lane << 2)]);
            acc[0].x += pj.x * v4.x; acc[0].y += pj.x * v4.y;
            acc[0].z += pj.x * v4.z; acc[0].w += pj.x * v4.w;
            acc[1].x += pj.y * v4.x; acc[1].y += pj.y * v4.y;
            acc[1].z += pj.y * v4.z; acc[1].w += pj.y * v4.w;
            acc[2].x += pj.z * v4.x; acc[2].y += pj.z * v4.y;
            acc[2].z += pj.z * v4.z; acc[2].w += pj.z * v4.w;
            acc[3].x += pj.w * v4.x; acc[3].y += pj.w * v4.y;
            acc[3].z += pj.w * v4.z; acc[3].w += pj.w * v4.w;
        }
        __syncwarp();
    }

#pragma unroll
    for (int r = 0; r < 4; r++) {
        const float inv = 1.0f / l[r];
        float4 o4 = make_float4(acc[r].x * inv, acc[r].y * inv,
                                acc[r].z * inv, acc[r].w * inv);
        *(float4*)(&g_O[(size_t)(qbase + r) * DMODEL + h * DHEAD + (lane << 2)]) = o4;
    }
}

/* ------------------------------------------------------------------ */
extern "C" void kernel_launch(void* const* d_in, const int* in_sizes, int n_in,
                              void* d_out, int out_size)
{
    const float* x        = (const float*)d_in[0];
    const float* Wq_down  = (const float*)d_in[1];
    const float* Wq_up    = (const float*)d_in[2];
    const float* Wq_rope  = (const float*)d_in[3];
    const float* Wkv_down = (const float*)d_in[4];
    const float* Wk_up    = (const float*)d_in[5];
    const float* Wv_up    = (const float*)d_in[6];
    const float* Wk_rope  = (const float*)d_in[7];
    const float* Wo       = (const float*)d_in[8];
    float* out = (float*)d_out;

    float *qd, *qc, *qr, *kv, *kc, *kr, *vu, *O;
    cudaGetSymbolAddress((void**)&qd, g_qd);
    cudaGetSymbolAddress((void**)&qc, g_qc);
    cudaGetSymbolAddress((void**)&qr, g_qr);
    cudaGetSymbolAddress((void**)&kv, g_kv);
    cudaGetSymbolAddress((void**)&kc, g_kc);
    cudaGetSymbolAddress((void**)&kr, g_kr);
    cudaGetSymbolAddress((void**)&vu, g_vu);
    cudaGetSymbolAddress((void**)&O,  g_O);

    const dim3 blk(256);

    /* projections (tensor-core split-bf16 GEMM) */
    gemm_mma<<<dim3( 4, 16), blk>>>(x,  Wq_down,  qd, 2048,  512, 2048);
    gemm_mma<<<dim3( 8, 16), blk>>>(qd, Wq_up,    qc, 2048, 1024,  512);
    gemm_mma<<<dim3( 8, 16), blk>>>(x,  Wq_rope,  qr, 2048, 1024, 2048);
    gemm_mma<<<dim3( 4, 16), blk>>>(x,  Wkv_down, kv, 2048,  512, 2048);
    gemm_mma<<<dim3( 8, 16), blk>>>(kv, Wk_up,    kc, 2048, 1024,  512);
    gemm_mma<<<dim3( 8, 16), blk>>>(x,  Wk_rope,  kr, 2048, 1024, 2048);
    gemm_mma<<<dim3(16, 16), blk>>>(kv, Wv_up,    vu, 2048, 2048,  512);

    /* rope + layout */
    pack_kernel<<<dim3(TSEQ, NH), 128>>>();

    /* causal attention */
    attn_kernel<<<dim3(TSEQ / 16, NH), 128>>>();

    /* output projection */
    gemm_mma<<<dim3(16, 16), blk>>>(O, Wo, out, 2048, 2048, 2048);
}

// round 3
// speedup vs baseline: 1.4405x; 1.1488x over previous
#include <cuda_runtime.h>
#include <cuda_bf16.h>
#include <math.h>
#include <stdint.h>

#define TSEQ   2048
#define DMODEL 2048
#define NH     16
#define DHEAD  128
#define DROPE  64
#define DCONT  64
#define SCALE_ATT 0.08838834764831845f  /* 1/sqrt(128) */

/* ------------------------------------------------------------------ */
/* Scratch (device globals)                                            */
/* ------------------------------------------------------------------ */
__device__ float g_qc[TSEQ * 1024];
__device__ float g_qr[TSEQ * 1024];
__device__ float g_kc[TSEQ * 1024];
__device__ float g_kr[TSEQ * 1024];
__device__ float g_vu[TSEQ * 2048];
__device__ float g_Q[NH * TSEQ * DHEAD];
__device__ float g_K[NH * TSEQ * DHEAD];
__device__ float g_V[NH * TSEQ * DHEAD];

/* bf16 hi/lo split operands */
__device__ __nv_bfloat16 g_xh[TSEQ * 2048],  g_xl[TSEQ * 2048];
__device__ __nv_bfloat16 g_qdh[TSEQ * 512],  g_qdl[TSEQ * 512];
__device__ __nv_bfloat16 g_kvh[TSEQ * 512],  g_kvl[TSEQ * 512];
__device__ __nv_bfloat16 g_Oh[TSEQ * 2048],  g_Ol[TSEQ * 2048];
__device__ __nv_bfloat16 g_wqdh[2048 * 512], g_wqdl[2048 * 512];
__device__ __nv_bfloat16 g_wquh[512 * 1024], g_wqul[512 * 1024];
__device__ __nv_bfloat16 g_wqrh[2048 * 1024],g_wqrl[2048 * 1024];
__device__ __nv_bfloat16 g_wkdh[2048 * 512], g_wkdl[2048 * 512];
__device__ __nv_bfloat16 g_wkuh[512 * 1024], g_wkul[512 * 1024];
__device__ __nv_bfloat16 g_wvuh[512 * 2048], g_wvul[512 * 2048];
__device__ __nv_bfloat16 g_wkrh[2048 * 1024],g_wkrl[2048 * 1024];
__device__ __nv_bfloat16 g_woh[2048 * 2048], g_wol[2048 * 2048];

/* ------------------------------------------------------------------ */
/* asm helpers                                                         */
/* ------------------------------------------------------------------ */
#define CPA16(dst, src)                                                    \
    asm volatile("cp.async.cg.shared.global [%0], [%1], 16;"               \
                 :: "r"(dst), "l"(src))
#define CPA_COMMIT() asm volatile("cp.async.commit_group;")
#define CPA_WAIT1()  asm volatile("cp.async.wait_group 1;")
#define CPA_WAIT0()  asm volatile("cp.async.wait_group 0;")

#define LDSM4(r0, r1, r2, r3, addr)                                        \
    asm volatile("ldmatrix.sync.aligned.m8n8.x4.shared.b16 {%0,%1,%2,%3}, [%4];" \
                 : "=r"(r0), "=r"(r1), "=r"(r2), "=r"(r3) : "r"(addr))
#define LDSM4T(r0, r1, r2, r3, addr)                                       \
    asm volatile("ldmatrix.sync.aligned.m8n8.x4.trans.shared.b16 {%0,%1,%2,%3}, [%4];" \
                 : "=r"(r0), "=r"(r1), "=r"(r2), "=r"(r3) : "r"(addr))
#define MMA_BF16(c, a, b0, b1)                                             \
    asm volatile("mma.sync.aligned.m16n8k16.row.col.f32.bf16.bf16.f32 "    \
                 "{%0,%1,%2,%3}, {%4,%5,%6,%7}, {%8,%9}, {%0,%1,%2,%3};"   \
                 : "+f"(c[0]), "+f"(c[1]), "+f"(c[2]), "+f"(c[3])          \
                 : "r"(a[0]), "r"(a[1]), "r"(a[2]), "r"(a[3]),             \
                   "r"(b0), "r"(b1))

__device__ __forceinline__ uint32_t bf2pack(float a, float b)
{
    return (uint32_t)__bfloat16_as_ushort(__float2bfloat16_rn(a)) |
           ((uint32_t)__bfloat16_as_ushort(__float2bfloat16_rn(b)) << 16);
}

/* ------------------------------------------------------------------ */
/* Batched fp32 -> bf16 hi/lo split                                    */
/* ------------------------------------------------------------------ */
struct SplitJob { const float* src; __nv_bfloat16 *h, *l; int n; };
struct SplitJobs { SplitJob j[9]; };

__global__ void __launch_bounds__(256) split_many(SplitJobs js)
{
    const SplitJob J = js.j[blockIdx.y];
    const int i = (blockIdx.x * 256 + threadIdx.x) << 2;
    if (i >= J.n) return;
    float4 v = *(const float4*)(J.src + i);
    float h0 = __bfloat162float(__float2bfloat16_rn(v.x));
    float h1 = __bfloat162float(__float2bfloat16_rn(v.y));
    float h2 = __bfloat162float(__float2bfloat16_rn(v.z));
    float h3 = __bfloat162float(__float2bfloat16_rn(v.w));
    uint2 hp, lp;
    hp.x = bf2pack(v.x, v.y);          hp.y = bf2pack(v.z, v.w);
    lp.x = bf2pack(v.x - h0, v.y - h1); lp.y = bf2pack(v.z - h2, v.w - h3);
    *(uint2*)(J.h + i) = hp;
    *(uint2*)(J.l + i) = lp;
}

/* ------------------------------------------------------------------ */
/* Fused multi-segment split-bf16 tensor-core GEMM                     */
/* BM=BN=128, BK=32, 256 threads (8 warps, 4x2), cp.async 2 stages.    */
/* smem XOR-swizzled; dynamic smem = 64KB.                             */
/* ------------------------------------------------------------------ */
struct GSeg {
    const __nv_bfloat16 *Ah, *Al;
    int lda;
    const __nv_bfloat16 *Bh, *Bl;
    float* Cf;                 /* fp32 out (or null)      */
    __nv_bfloat16 *Ch, *Cl;    /* bf16 split out (or null)*/
    int N, K, tile0;
};
struct GSegs { GSeg s[4]; int n; };

#define STAGE_BYTES 32768
#define A_LO_OFF    8192
#define B_HI_OFF    16384
#define B_LO_OFF    24576

/* A: 128 rows x 4 chunks(16B). B: 32 rows x 16 chunks(16B). */
__device__ __forceinline__ uint32_t offA(int r, int c)
{ return (uint32_t)(((r << 2) + (c ^ ((r >> 1) & 3))) << 4); }
__device__ __forceinline__ uint32_t offB(int r, int c)
{ return (uint32_t)(((r << 4) + (c ^ (r & 7))) << 4); }

__global__ void __launch_bounds__(256) gemm_fused(GSegs segs)
{
    extern __shared__ char dsm[];
    const uint32_t sb = (uint32_t)__cvta_generic_to_shared(dsm);

    const int tid  = threadIdx.x;
    const int lane = tid & 31;
    const int warp = tid >> 5;
    const int wm   = (warp >> 1) << 5;
    const int wn   = (warp & 1) << 6;
    const int bm   = blockIdx.y << 7;

    /* segment select */
    GSeg sg = segs.s[0];
#pragma unroll
    for (int i = 1; i < 4; i++)
        if (i < segs.n && (int)blockIdx.x >= segs.s[i].tile0) sg = segs.s[i];
    const int bn  = ((int)blockIdx.x - sg.tile0) << 7;
    const int lda = sg.lda, ldb = sg.N, K = sg.K;

    /* loader indices */
    const int ar = tid >> 2, ac = tid & 3;       /* A: rows ar, ar+64 */
    const int br = tid >> 3, bc = tid & 7;       /* B: row br, chunks bc, bc+8 */
    const uint32_t aoff0 = offA(ar, ac), aoff1 = offA(ar + 64, ac);
    const uint32_t boff0 = offB(br, bc), boff1 = offB(br, bc + 8);

    const __nv_bfloat16* gAh = sg.Ah + (size_t)(bm + ar) * lda + ac * 8;
    const __nv_bfloat16* gAl = sg.Al + (size_t)(bm + ar) * lda + ac * 8;
    const __nv_bfloat16* gBh = sg.Bh + (size_t)br * ldb + bn + bc * 8;
    const __nv_bfloat16* gBl = sg.Bl + (size_t)br * ldb + bn + bc * 8;

    float acc[2][8][4];
#pragma unroll
    for (int mt = 0; mt < 2; mt++)
#pragma unroll
        for (int nt = 0; nt < 8; nt++)
#pragma unroll
            for (int i = 0; i < 4; i++) acc[mt][nt][i] = 0.f;

    const int nk = K >> 5;

    /* ---- stage loader ---- */
    auto load_stage = [&](int st, int k0) {
        const uint32_t s0 = sb + st * STAGE_BYTES;
        const __nv_bfloat16* pAh = gAh + k0;
        const __nv_bfloat16* pAl = gAl + k0;
        CPA16(s0 + aoff0, pAh);
        CPA16(s0 + aoff1, pAh + (size_t)64 * lda);
        CPA16(s0 + A_LO_OFF + aoff0, pAl);
        CPA16(s0 + A_LO_OFF + aoff1, pAl + (size_t)64 * lda);
        const __nv_bfloat16* pBh = gBh + (size_t)k0 * ldb;
        const __nv_bfloat16* pBl = gBl + (size_t)k0 * ldb;
        CPA16(s0 + B_HI_OFF + boff0, pBh);
        CPA16(s0 + B_HI_OFF + boff1, pBh + 64);
        CPA16(s0 + B_LO_OFF + boff0, pBl);
        CPA16(s0 + B_LO_OFF + boff1, pBl + 64);
    };

    load_stage(0, 0);
    CPA_COMMIT();

    for (int it = 0; it < nk; it++) {
        if (it + 1 < nk) { load_stage((it + 1) & 1, (it + 1) << 5); CPA_COMMIT(); }
        if (it + 1 < nk) CPA_WAIT1(); else CPA_WAIT0();
        __syncthreads();

        const uint32_t s0 = sb + (it & 1) * STAGE_BYTES;
#pragma unroll
        for (int ks = 0; ks < 2; ks++) {
            uint32_t ah[2][4], al_[2][4];
#pragma unroll
            for (int mt = 0; mt < 2; mt++) {
                const int rowA   = wm + (mt << 4) + (lane & 15);
                const int chunkA = (ks << 1) + (lane >> 4);
                const uint32_t ad = s0 + offA(rowA, chunkA);
                LDSM4(ah[mt][0], ah[mt][1], ah[mt][2], ah[mt][3], ad);
                LDSM4(al_[mt][0], al_[mt][1], al_[mt][2], al_[mt][3], ad + A_LO_OFF);
            }
            uint32_t bhf[8][2], blf[8][2];
#pragma unroll
            for (int np = 0; np < 4; np++) {
                const int rowB   = (ks << 4) + (lane & 15);
                const int chunkB = (wn >> 3) + (lane >> 4) + (np << 1);
                const uint32_t bd = s0 + B_HI_OFF + offB(rowB, chunkB);
                uint32_t r0, r1, r2, r3;
                LDSM4T(r0, r1, r2, r3, bd);
                bhf[2 * np][0] = r0; bhf[2 * np][1] = r1;
                bhf[2 * np + 1][0] = r2; bhf[2 * np + 1][1] = r3;
                LDSM4T(r0, r1, r2, r3, bd + 8192);
                blf[2 * np][0] = r0; blf[2 * np][1] = r1;
                blf[2 * np + 1][0] = r2; blf[2 * np + 1][1] = r3;
            }
#pragma unroll
            for (int mt = 0; mt < 2; mt++)
#pragma unroll
                for (int nt = 0; nt < 8; nt++) {
                    MMA_BF16(acc[mt][nt], ah[mt],  bhf[nt][0], bhf[nt][1]);
                    MMA_BF16(acc[mt][nt], ah[mt],  blf[nt][0], blf[nt][1]);
                    MMA_BF16(acc[mt][nt], al_[mt], bhf[nt][0], bhf[nt][1]);
                }
        }
        __syncthreads();
    }

    /* epilogue */
    const int erow = lane >> 2;
    const int ecol = (lane & 3) << 1;
    if (sg.Cf) {
#pragma unroll
        for (int mt = 0; mt < 2; mt++)
#pragma unroll
            for (int nt = 0; nt < 8; nt++) {
                const int r = bm + wm + (mt << 4) + erow;
                const int c = bn + wn + (nt << 3) + ecol;
                *(float2*)(sg.Cf + (size_t)r * ldb + c) =
                    make_float2(acc[mt][nt][0], acc[mt][nt][1]);
                *(float2*)(sg.Cf + (size_t)(r + 8) * ldb + c) =
                    make_float2(acc[mt][nt][2], acc[mt][nt][3]);
            }
    } else {
#pragma unroll
        for (int mt = 0; mt < 2; mt++)
#pragma unroll
            for (int nt = 0; nt < 8; nt++) {
                const int r = bm + wm + (mt << 4) + erow;
                const int c = bn + wn + (nt << 3) + ecol;
#pragma unroll
                for (int hh = 0; hh < 2; hh++) {
                    const float v0 = acc[mt][nt][2 * hh];
                    const float v1 = acc[mt][nt][2 * hh + 1];
                    const float h0 = __bfloat162float(__float2bfloat16_rn(v0));
                    const float h1 = __bfloat162float(__float2bfloat16_rn(v1));
                    const size_t idx = (size_t)(r + 8 * hh) * ldb + c;
                    *(uint32_t*)(sg.Ch + idx) = bf2pack(v0, v1);
                    *(uint32_t*)(sg.Cl + idx) = bf2pack(v0 - h0, v1 - h1);
                }
            }
    }
}

/* ------------------------------------------------------------------ */
/* Pack + RoPE: builds Q/K/V in [h][t][d] layout.                      */
/* ------------------------------------------------------------------ */
__global__ void __launch_bounds__(128) pack_kernel()
{
    const int t = blockIdx.x;
    const int h = blockIdx.y;
    const int d = threadIdx.x;
    const size_t oidx = ((size_t)h * TSEQ + t) * DHEAD + d;

    g_V[oidx] = g_vu[(size_t)t * 2048 + h * DHEAD + d];

    float qv, kvv;
    if (d < DCONT) {
        qv  = g_qc[(size_t)t * 1024 + h * DCONT + d];
        kvv = g_kc[(size_t)t * 1024 + h * DCONT + d];
    } else {
        const int i  = d - DCONT;
        const int ip = (i < 32) ? i : i - 32;
        const double inv = pow(10000.0, -(double)ip / 32.0);
        double sd, cd;
        sincos((double)t * inv, &sd, &cd);
        const float c = (float)cd, s = (float)sd;
        const size_t rbase = (size_t)t * 1024 + h * DROPE;
        const float q1 = g_qr[rbase + ip];
        const float q2 = g_qr[rbase + 32 + ip];
        const float k1 = g_kr[rbase + ip];
        const float k2 = g_kr[rbase + 32 + ip];
        if (i < 32) { qv = q1 * c - q2 * s;  kvv = k1 * c - k2 * s; }
        else        { qv = q1 * s + q2 * c;  kvv = k1 * s + k2 * c; }
    }
    g_Q[oidx] = qv;
    g_K[oidx] = kvv;
}

/* ------------------------------------------------------------------ */
/* Causal flash attention, fp32. Writes O as bf16 hi/lo.               */
/* ------------------------------------------------------------------ */
__global__ void __launch_bounds__(128) attn_kernel()
{
    __shared__ float kT[128 * 36];
    __shared__ float vs[32 * 128];
    __shared__ float qsT[128 * 16];
    __shared__ float psh[4 * 128];

    const int h     = blockIdx.y;
    const int warp  = threadIdx.x >> 5;
    const int lane  = threadIdx.x & 31;
    const int q0blk = blockIdx.x << 4;

    const float* Kb = g_K + (size_t)h * TSEQ * DHEAD;
    const float* Vb = g_V + (size_t)h * TSEQ * DHEAD;
    const float* Qb = g_Q + (size_t)h * TSEQ * DHEAD;

    {
        const int r  = threadIdx.x & 15;
        const int d4 = (threadIdx.x >> 4) << 2;
        for (int dd = d4; dd < 128; dd += 32) {
            float4 q4 = *(const float4*)(Qb + (size_t)(q0blk + r) * DHEAD + dd);
            qsT[(dd + 0) * 16 + r] = q4.x;
            qsT[(dd + 1) * 16 + r] = q4.y;
            qsT[(dd + 2) * 16 + r] = q4.z;
            qsT[(dd + 3) * 16 + r] = q4.w;
        }
    }

    float  m[4], l[4];
    float4 acc[4];
#pragma unroll
    for (int r = 0; r < 4; r++) {
        m[r] = -1e30f; l[r] = 0.f;
        acc[r] = make_float4(0.f, 0.f, 0.f, 0.f);
    }

    const int qbase  = q0blk + (warp << 2);
    const int ntiles = (q0blk + 15) / 32 + 1;

    for (int tile = 0; tile < ntiles; tile++) {
        const int kb = tile << 5;
        __syncthreads();
#pragma unroll
        for (int kk = warp; kk < 32; kk += 4) {
            const int d0 = lane << 2;
            float4 k4 = *(const float4*)(Kb + (size_t)(kb + kk) * DHEAD + d0);
            kT[(d0 + 0) * 36 + kk] = k4.x;
            kT[(d0 + 1) * 36 + kk] = k4.y;
            kT[(d0 + 2) * 36 + kk] = k4.z;
            kT[(d0 + 3) * 36 + kk] = k4.w;
            *(float4*)(&vs[kk * 128 + d0]) =
                *(const float4*)(Vb + (size_t)(kb + kk) * DHEAD + d0);
        }
        __syncthreads();

        float s[4] = {0.f, 0.f, 0.f, 0.f};
#pragma unroll 16
        for (int d = 0; d < 128; d++) {
            const float  kv = kT[d * 36 + lane];
            const float4 q4 = *(const float4*)(&qsT[d * 16 + (warp << 2)]);
            s[0] += kv * q4.x;
            s[1] += kv * q4.y;
            s[2] += kv * q4.z;
            s[3] += kv * q4.w;
        }

        const int key = kb + lane;
        float p[4];
#pragma unroll
        for (int r = 0; r < 4; r++) {
            float sv = s[r] * SCALE_ATT;
            if (key > qbase + r) sv = -1e30f;
            float mc = sv;
#pragma unroll
            for (int o = 16; o; o >>= 1)
                mc = fmaxf(mc, __shfl_xor_sync(0xffffffffu, mc, o));
            const float mn    = fmaxf(m[r], mc);
            const float alpha = __expf(m[r] - mn);
            const float pv    = __expf(sv - mn);
            float ps = pv;
#pragma unroll
            for (int o = 16; o; o >>= 1)
                ps += __shfl_xor_sync(0xffffffffu, ps, o);
            l[r] = l[r] * alpha + ps;
            acc[r].x *= alpha; acc[r].y *= alpha;
            acc[r].z *= alpha; acc[r].w *= alpha;
            m[r] = mn;
            p[r] = pv;
        }

        *(float4*)(&psh[warp * 128 + (lane << 2)]) =
            make_float4(p[0], p[1], p[2], p[3]);
        __syncwarp();

#pragma unroll 8
        for (int j = 0; j < 32; j++) {
            const float4 pj = *(const float4*)(&psh[warp * 128 + (j << 2)]);
            const float4 v4 = *(const float4*)(&vs[j * 128 + (lane << 2)]);
            acc[0].x += pj.x * v4.x; acc[0].y += pj.x * v4.y;
            acc[0].z += pj.x * v4.z; acc[0].w += pj.x * v4.w;
            acc[1].x += pj.y * v4.x; acc[1].y += pj.y * v4.y;
            acc[1].z += pj.y * v4.z; acc[1].w += pj.y * v4.w;
            acc[2].x += pj.z * v4.x; acc[2].y += pj.z * v4.y;
            acc[2].z += pj.z * v4.z; acc[2].w += pj.z * v4.w;
            acc[3].x += pj.w * v4.x; acc[3].y += pj.w * v4.y;
            acc[3].z += pj.w * v4.z; acc[3].w += pj.w * v4.w;
        }
        __syncwarp();
    }

#pragma unroll
    for (int r = 0; r < 4; r++) {
        const float inv = 1.0f / l[r];
        const float v0 = acc[r].x * inv, v1 = acc[r].y * inv;
        const float v2 = acc[r].z * inv, v3 = acc[r].w * inv;
        const float h0 = __bfloat162float(__float2bfloat16_rn(v0));
        const float h1 = __bfloat162float(__float2bfloat16_rn(v1));
        const float h2 = __bfloat162float(__float2bfloat16_rn(v2));
        const float h3 = __bfloat162float(__float2bfloat16_rn(v3));
        const size_t idx = (size_t)(qbase + r) * DMODEL + h * DHEAD + (lane << 2);
        uint2 hp, lp;
        hp.x = bf2pack(v0, v1);           hp.y = bf2pack(v2, v3);
        lp.x = bf2pack(v0 - h0, v1 - h1); lp.y = bf2pack(v2 - h2, v3 - h3);
        *(uint2*)(g_Oh + idx) = hp;
        *(uint2*)(g_Ol + idx) = lp;
    }
}

/* ------------------------------------------------------------------ */
extern "C" void kernel_launch(void* const* d_in, const int* in_sizes, int n_in,
                              void* d_out, int out_size)
{
    const float* x        = (const float*)d_in[0];
    const float* Wq_down  = (const float*)d_in[1];
    const float* Wq_up    = (const float*)d_in[2];
    const float* Wq_rope  = (const float*)d_in[3];
    const float* Wkv_down = (const float*)d_in[4];
    const float* Wk_up    = (const float*)d_in[5];
    const float* Wv_up    = (const float*)d_in[6];
    const float* Wk_rope  = (const float*)d_in[7];
    const float* Wo       = (const float*)d_in[8];
    float* out = (float*)d_out;

    /* symbol addresses */
    float *qc, *qr, *kc, *kr, *vu;
    cudaGetSymbolAddress((void**)&qc, g_qc);
    cudaGetSymbolAddress((void**)&qr, g_qr);
    cudaGetSymbolAddress((void**)&kc, g_kc);
    cudaGetSymbolAddress((void**)&kr, g_kr);
    cudaGetSymbolAddress((void**)&vu, g_vu);

    __nv_bfloat16 *xh, *xl, *qdh, *qdl, *kvh, *kvl, *Oh, *Ol;
    __nv_bfloat16 *wqdh, *wqdl, *wquh, *wqul, *wqrh, *wqrl, *wkdh, *wkdl;
    __nv_bfloat16 *wkuh, *wkul, *wvuh, *wvul, *wkrh, *wkrl, *woh, *wol;
    cudaGetSymbolAddress((void**)&xh, g_xh);   cudaGetSymbolAddress((void**)&xl, g_xl);
    cudaGetSymbolAddress((void**)&qdh, g_qdh); cudaGetSymbolAddress((void**)&qdl, g_qdl);
    cudaGetSymbolAddress((void**)&kvh, g_kvh); cudaGetSymbolAddress((void**)&kvl, g_kvl);
    cudaGetSymbolAddress((void**)&Oh, g_Oh);   cudaGetSymbolAddress((void**)&Ol, g_Ol);
    cudaGetSymbolAddress((void**)&wqdh, g_wqdh); cudaGetSymbolAddress((void**)&wqdl, g_wqdl);
    cudaGetSymbolAddress((void**)&wquh, g_wquh); cudaGetSymbolAddress((void**)&wqul, g_wqul);
    cudaGetSymbolAddress((void**)&wqrh, g_wqrh); cudaGetSymbolAddress((void**)&wqrl, g_wqrl);
    cudaGetSymbolAddress((void**)&wkdh, g_wkdh); cudaGetSymbolAddress((void**)&wkdl, g_wkdl);
    cudaGetSymbolAddress((void**)&wkuh, g_wkuh); cudaGetSymbolAddress((void**)&wkul, g_wkul);
    cudaGetSymbolAddress((void**)&wvuh, g_wvuh); cudaGetSymbolAddress((void**)&wvul, g_wvul);
    cudaGetSymbolAddress((void**)&wkrh, g_wkrh); cudaGetSymbolAddress((void**)&wkrl, g_wkrl);
    cudaGetSymbolAddress((void**)&woh, g_woh);   cudaGetSymbolAddress((void**)&wol, g_wol);

    cudaFuncSetAttribute(gemm_fused,
                         cudaFuncAttributeMaxDynamicSharedMemorySize, 65536);

    /* 1. split inputs + weights to bf16 hi/lo */
    SplitJobs js;
    js.j[0] = { x,        xh,   xl,   TSEQ * 2048 };
    js.j[1] = { Wq_down,  wqdh, wqdl, 2048 * 512  };
    js.j[2] = { Wq_up,    wquh, wqul, 512 * 1024  };
    js.j[3] = { Wq_rope,  wqrh, wqrl, 2048 * 1024 };
    js.j[4] = { Wkv_down, wkdh, wkdl, 2048 * 512  };
    js.j[5] = { Wk_up,    wkuh, wkul, 512 * 1024  };
    js.j[6] = { Wv_up,    wvuh, wvul, 512 * 2048  };
    js.j[7] = { Wk_rope,  wkrh, wkrl, 2048 * 1024 };
    js.j[8] = { Wo,       woh,  wol,  2048 * 2048 };
    split_many<<<dim3(4096, 9), 256>>>(js);

    /* 2. GEMM1: x @ [Wq_down | Wkv_down | Wq_rope | Wk_rope] */
    {
        GSegs g; g.n = 4;
        g.s[0] = { xh, xl, 2048, wqdh, wqdl, nullptr, qdh, qdl,  512, 2048, 0  };
        g.s[1] = { xh, xl, 2048, wkdh, wkdl, nullptr, kvh, kvl,  512, 2048, 4  };
        g.s[2] = { xh, xl, 2048, wqrh, wqrl, qr, nullptr, nullptr, 1024, 2048, 8  };
        g.s[3] = { xh, xl, 2048, wkrh, wkrl, kr, nullptr, nullptr, 1024, 2048, 16 };
        gemm_fused<<<dim3(24, 16), 256, 65536>>>(g);
    }

    /* 3. GEMM2: qd @ Wq_up ; kv @ [Wk_up | Wv_up] */
    {
        GSegs g; g.n = 3;
        g.s[0] = { qdh, qdl, 512, wquh, wqul, qc, nullptr, nullptr, 1024, 512, 0  };
        g.s[1] = { kvh, kvl, 512, wkuh, wkul, kc, nullptr, nullptr, 1024, 512, 8  };
        g.s[2] = { kvh, kvl, 512, wvuh, wvul, vu, nullptr, nullptr, 2048, 512, 16 };
        g.s[3] = g.s[0];
        gemm_fused<<<dim3(32, 16), 256, 65536>>>(g);
    }

    /* 4. rope + layout */
    pack_kernel<<<dim3(TSEQ, NH), 128>>>();

    /* 5. causal attention (writes O as bf16 hi/lo) */
    attn_kernel<<<dim3(TSEQ / 16, NH), 128>>>();

    /* 6. GEMM3: O @ Wo -> out */
    {
        GSegs g; g.n = 1;
        g.s[0] = { Oh, Ol, 2048, woh, wol, out, nullptr, nullptr, 2048, 2048, 0 };
        g.s[1] = g.s[0]; g.s[2] = g.s[0]; g.s[3] = g.s[0];
        gemm_fused<<<dim3(16, 16), 256, 65536>>>(g);
    }
}

// round 4
// speedup vs baseline: 1.7701x; 1.2288x over previous
#include <cuda_runtime.h>
#include <cuda_bf16.h>
#include <math.h>
#include <stdint.h>

#define TSEQ   2048
#define DMODEL 2048
#define NH     16
#define DHEAD  128
#define DROPE  64
#define DCONT  64
#define SCALE_ATT 0.08838834764831845f  /* 1/sqrt(128) */

/* ------------------------------------------------------------------ */
/* Scratch (device globals)                                            */
/* ------------------------------------------------------------------ */
__device__ float g_qc[TSEQ * 1024];
__device__ float g_qr[TSEQ * 1024];
__device__ float g_kc[TSEQ * 1024];
__device__ float g_kr[TSEQ * 1024];
__device__ float g_vu[TSEQ * 2048];
__device__ float g_Q[NH * TSEQ * DHEAD];
__device__ float g_K[NH * TSEQ * DHEAD];
__device__ float g_cosT[TSEQ * 32];
__device__ float g_sinT[TSEQ * 32];

/* bf16 hi/lo split operands */
__device__ __nv_bfloat16 g_xh[TSEQ * 2048],  g_xl[TSEQ * 2048];
__device__ __nv_bfloat16 g_qdh[TSEQ * 512],  g_qdl[TSEQ * 512];
__device__ __nv_bfloat16 g_kvh[TSEQ * 512],  g_kvl[TSEQ * 512];
__device__ __nv_bfloat16 g_Oh[TSEQ * 2048],  g_Ol[TSEQ * 2048];
__device__ __nv_bfloat16 g_wqdh[2048 * 512], g_wqdl[2048 * 512];
__device__ __nv_bfloat16 g_wquh[512 * 1024], g_wqul[512 * 1024];
__device__ __nv_bfloat16 g_wqrh[2048 * 1024],g_wqrl[2048 * 1024];
__device__ __nv_bfloat16 g_wkdh[2048 * 512], g_wkdl[2048 * 512];
__device__ __nv_bfloat16 g_wkuh[512 * 1024], g_wkul[512 * 1024];
__device__ __nv_bfloat16 g_wvuh[512 * 2048], g_wvul[512 * 2048];
__device__ __nv_bfloat16 g_wkrh[2048 * 1024],g_wkrl[2048 * 1024];
__device__ __nv_bfloat16 g_woh[2048 * 2048], g_wol[2048 * 2048];

/* ------------------------------------------------------------------ */
/* asm helpers                                                         */
/* ------------------------------------------------------------------ */
#define CPA16(dst, src)                                                    \
    asm volatile("cp.async.cg.shared.global [%0], [%1], 16;"               \
                 :: "r"(dst), "l"(src))
#define CPA_COMMIT() asm volatile("cp.async.commit_group;")
#define CPA_WAIT1()  asm volatile("cp.async.wait_group 1;")
#define CPA_WAIT0()  asm volatile("cp.async.wait_group 0;")

#define LDSM4(r0, r1, r2, r3, addr)                                        \
    asm volatile("ldmatrix.sync.aligned.m8n8.x4.shared.b16 {%0,%1,%2,%3}, [%4];" \
                 : "=r"(r0), "=r"(r1), "=r"(r2), "=r"(r3) : "r"(addr))
#define LDSM4T(r0, r1, r2, r3, addr)                                       \
    asm volatile("ldmatrix.sync.aligned.m8n8.x4.trans.shared.b16 {%0,%1,%2,%3}, [%4];" \
                 : "=r"(r0), "=r"(r1), "=r"(r2), "=r"(r3) : "r"(addr))
#define MMA_BF16(c, a, b0, b1)                                             \
    asm volatile("mma.sync.aligned.m16n8k16.row.col.f32.bf16.bf16.f32 "    \
                 "{%0,%1,%2,%3}, {%4,%5,%6,%7}, {%8,%9}, {%0,%1,%2,%3};"   \
                 : "+f"(c[0]), "+f"(c[1]), "+f"(c[2]), "+f"(c[3])          \
                 : "r"(a[0]), "r"(a[1]), "r"(a[2]), "r"(a[3]),             \
                   "r"(b0), "r"(b1))

__device__ __forceinline__ uint32_t bf2pack(float a, float b)
{
    return (uint32_t)__bfloat16_as_ushort(__float2bfloat16_rn(a)) |
           ((uint32_t)__bfloat16_as_ushort(__float2bfloat16_rn(b)) << 16);
}

/* ------------------------------------------------------------------ */
/* RoPE table: 2048 x 32 (fp64 once, then fp32 everywhere)             */
/* ------------------------------------------------------------------ */
__global__ void __launch_bounds__(256) rope_table()
{
    const int idx = blockIdx.x * 256 + threadIdx.x;
    if (idx >= TSEQ * 32) return;
    const int t = idx >> 5, i = idx & 31;
    const double inv = pow(10000.0, -(double)i / 32.0);
    double sd, cd;
    sincos((double)t * inv, &sd, &cd);
    g_cosT[idx] = (float)cd;
    g_sinT[idx] = (float)sd;
}

/* ------------------------------------------------------------------ */
/* Batched fp32 -> bf16 hi/lo split                                    */
/* ------------------------------------------------------------------ */
struct SplitJob { const float* src; __nv_bfloat16 *h, *l; int n; };
struct SplitJobs { SplitJob j[9]; };

__global__ void __launch_bounds__(256) split_many(SplitJobs js)
{
    const SplitJob J = js.j[blockIdx.y];
    const int i = (blockIdx.x * 256 + threadIdx.x) << 2;
    if (i >= J.n) return;
    float4 v = *(const float4*)(J.src + i);
    float h0 = __bfloat162float(__float2bfloat16_rn(v.x));
    float h1 = __bfloat162float(__float2bfloat16_rn(v.y));
    float h2 = __bfloat162float(__float2bfloat16_rn(v.z));
    float h3 = __bfloat162float(__float2bfloat16_rn(v.w));
    uint2 hp, lp;
    hp.x = bf2pack(v.x, v.y);          hp.y = bf2pack(v.z, v.w);
    lp.x = bf2pack(v.x - h0, v.y - h1); lp.y = bf2pack(v.z - h2, v.w - h3);
    *(uint2*)(J.h + i) = hp;
    *(uint2*)(J.l + i) = lp;
}

/* ------------------------------------------------------------------ */
/* Fused multi-segment split-bf16 tensor-core GEMM                     */
/* ------------------------------------------------------------------ */
struct GSeg {
    const __nv_bfloat16 *Ah, *Al;
    int lda;
    const __nv_bfloat16 *Bh, *Bl;
    float* Cf;
    __nv_bfloat16 *Ch, *Cl;
    int N, K, tile0;
};
struct GSegs { GSeg s[4]; int n; };

#define STAGE_BYTES 32768
#define A_LO_OFF    8192
#define B_HI_OFF    16384
#define B_LO_OFF    24576

__device__ __forceinline__ uint32_t offA(int r, int c)
{ return (uint32_t)(((r << 2) + (c ^ ((r >> 1) & 3))) << 4); }
__device__ __forceinline__ uint32_t offB(int r, int c)
{ return (uint32_t)(((r << 4) + (c ^ (r & 7))) << 4); }

__global__ void __launch_bounds__(256) gemm_fused(GSegs segs)
{
    extern __shared__ char dsm[];
    const uint32_t sb = (uint32_t)__cvta_generic_to_shared(dsm);

    const int tid  = threadIdx.x;
    const int lane = tid & 31;
    const int warp = tid >> 5;
    const int wm   = (warp >> 1) << 5;
    const int wn   = (warp & 1) << 6;
    const int bm   = blockIdx.y << 7;

    GSeg sg = segs.s[0];
#pragma unroll
    for (int i = 1; i < 4; i++)
        if (i < segs.n && (int)blockIdx.x >= segs.s[i].tile0) sg = segs.s[i];
    const int bn  = ((int)blockIdx.x - sg.tile0) << 7;
    const int lda = sg.lda, ldb = sg.N, K = sg.K;

    const int ar = tid >> 2, ac = tid & 3;
    const int br = tid >> 3, bc = tid & 7;
    const uint32_t aoff0 = offA(ar, ac), aoff1 = offA(ar + 64, ac);
    const uint32_t boff0 = offB(br, bc), boff1 = offB(br, bc + 8);

    const __nv_bfloat16* gAh = sg.Ah + (size_t)(bm + ar) * lda + ac * 8;
    const __nv_bfloat16* gAl = sg.Al + (size_t)(bm + ar) * lda + ac * 8;
    const __nv_bfloat16* gBh = sg.Bh + (size_t)br * ldb + bn + bc * 8;
    const __nv_bfloat16* gBl = sg.Bl + (size_t)br * ldb + bn + bc * 8;

    float acc[2][8][4];
#pragma unroll
    for (int mt = 0; mt < 2; mt++)
#pragma unroll
        for (int nt = 0; nt < 8; nt++)
#pragma unroll
            for (int i = 0; i < 4; i++) acc[mt][nt][i] = 0.f;

    const int nk = K >> 5;

    auto load_stage = [&](int st, int k0) {
        const uint32_t s0 = sb + st * STAGE_BYTES;
        const __nv_bfloat16* pAh = gAh + k0;
        const __nv_bfloat16* pAl = gAl + k0;
        CPA16(s0 + aoff0, pAh);
        CPA16(s0 + aoff1, pAh + (size_t)64 * lda);
        CPA16(s0 + A_LO_OFF + aoff0, pAl);
        CPA16(s0 + A_LO_OFF + aoff1, pAl + (size_t)64 * lda);
        const __nv_bfloat16* pBh = gBh + (size_t)k0 * ldb;
        const __nv_bfloat16* pBl = gBl + (size_t)k0 * ldb;
        CPA16(s0 + B_HI_OFF + boff0, pBh);
        CPA16(s0 + B_HI_OFF + boff1, pBh + 64);
        CPA16(s0 + B_LO_OFF + boff0, pBl);
        CPA16(s0 + B_LO_OFF + boff1, pBl + 64);
    };

    load_stage(0, 0);
    CPA_COMMIT();

    for (int it = 0; it < nk; it++) {
        if (it + 1 < nk) { load_stage((it + 1) & 1, (it + 1) << 5); CPA_COMMIT(); }
        if (it + 1 < nk) CPA_WAIT1(); else CPA_WAIT0();
        __syncthreads();

        const uint32_t s0 = sb + (it & 1) * STAGE_BYTES;
#pragma unroll
        for (int ks = 0; ks < 2; ks++) {
            uint32_t ah[2][4], al_[2][4];
#pragma unroll
            for (int mt = 0; mt < 2; mt++) {
                const int rowA   = wm + (mt << 4) + (lane & 15);
                const int chunkA = (ks << 1) + (lane >> 4);
                const uint32_t ad = s0 + offA(rowA, chunkA);
                LDSM4(ah[mt][0], ah[mt][1], ah[mt][2], ah[mt][3], ad);
                LDSM4(al_[mt][0], al_[mt][1], al_[mt][2], al_[mt][3], ad + A_LO_OFF);
            }
            uint32_t bhf[8][2], blf[8][2];
#pragma unroll
            for (int np = 0; np < 4; np++) {
                const int rowB   = (ks << 4) + (lane & 15);
                const int chunkB = (wn >> 3) + (lane >> 4) + (np << 1);
                const uint32_t bd = s0 + B_HI_OFF + offB(rowB, chunkB);
                uint32_t r0, r1, r2, r3;
                LDSM4T(r0, r1, r2, r3, bd);
                bhf[2 * np][0] = r0; bhf[2 * np][1] = r1;
                bhf[2 * np + 1][0] = r2; bhf[2 * np + 1][1] = r3;
                LDSM4T(r0, r1, r2, r3, bd + 8192);
                blf[2 * np][0] = r0; blf[2 * np][1] = r1;
                blf[2 * np + 1][0] = r2; blf[2 * np + 1][1] = r3;
            }
#pragma unroll
            for (int mt = 0; mt < 2; mt++)
#pragma unroll
                for (int nt = 0; nt < 8; nt++) {
                    MMA_BF16(acc[mt][nt], ah[mt],  bhf[nt][0], bhf[nt][1]);
                    MMA_BF16(acc[mt][nt], ah[mt],  blf[nt][0], blf[nt][1]);
                    MMA_BF16(acc[mt][nt], al_[mt], bhf[nt][0], bhf[nt][1]);
                }
        }
        __syncthreads();
    }

    const int erow = lane >> 2;
    const int ecol = (lane & 3) << 1;
    if (sg.Cf) {
#pragma unroll
        for (int mt = 0; mt < 2; mt++)
#pragma unroll
            for (int nt = 0; nt < 8; nt++) {
                const int r = bm + wm + (mt << 4) + erow;
                const int c = bn + wn + (nt << 3) + ecol;
                *(float2*)(sg.Cf + (size_t)r * ldb + c) =
                    make_float2(acc[mt][nt][0], acc[mt][nt][1]);
                *(float2*)(sg.Cf + (size_t)(r + 8) * ldb + c) =
                    make_float2(acc[mt][nt][2], acc[mt][nt][3]);
            }
    } else {
#pragma unroll
        for (int mt = 0; mt < 2; mt++)
#pragma unroll
            for (int nt = 0; nt < 8; nt++) {
                const int r = bm + wm + (mt << 4) + erow;
                const int c = bn + wn + (nt << 3) + ecol;
#pragma unroll
                for (int hh = 0; hh < 2; hh++) {
                    const float v0 = acc[mt][nt][2 * hh];
                    const float v1 = acc[mt][nt][2 * hh + 1];
                    const float h0 = __bfloat162float(__float2bfloat16_rn(v0));
                    const float h1 = __bfloat162float(__float2bfloat16_rn(v1));
                    const size_t idx = (size_t)(r + 8 * hh) * ldb + c;
                    *(uint32_t*)(sg.Ch + idx) = bf2pack(v0, v1);
                    *(uint32_t*)(sg.Cl + idx) = bf2pack(v0 - h0, v1 - h1);
                }
            }
    }
}

/* ------------------------------------------------------------------ */
/* Pack + RoPE: builds Q/K in [h][t][d] layout (table-driven).         */
/* ------------------------------------------------------------------ */
__global__ void __launch_bounds__(128) pack_kernel()
{
    const int t = blockIdx.x;
    const int h = blockIdx.y;
    const int d = threadIdx.x;
    const size_t oidx = ((size_t)h * TSEQ + t) * DHEAD + d;

    float qv, kvv;
    if (d < DCONT) {
        qv  = g_qc[(size_t)t * 1024 + h * DCONT + d];
        kvv = g_kc[(size_t)t * 1024 + h * DCONT + d];
    } else {
        const int i  = d - DCONT;
        const int ip = (i < 32) ? i : i - 32;
        const float c = g_cosT[t * 32 + ip];
        const float s = g_sinT[t * 32 + ip];
        const size_t rbase = (size_t)t * 1024 + h * DROPE;
        const float q1 = g_qr[rbase + ip];
        const float q2 = g_qr[rbase + 32 + ip];
        const float k1 = g_kr[rbase + ip];
        const float k2 = g_kr[rbase + 32 + ip];
        if (i < 32) { qv = q1 * c - q2 * s;  kvv = k1 * c - k2 * s; }
        else        { qv = q1 * s + q2 * c;  kvv = k1 * s + k2 * c; }
    }
    g_Q[oidx] = qv;
    g_K[oidx] = kvv;
}

/* ------------------------------------------------------------------ */
/* Causal flash attention, fp32. V read from g_vu (stride 2048).       */
/* Writes O as bf16 hi/lo.                                             */
/* ------------------------------------------------------------------ */
__global__ void __launch_bounds__(128) attn_kernel()
{
    __shared__ float kT[128 * 36];
    __shared__ float vs[32 * 128];
    __shared__ float qsT[128 * 16];
    __shared__ float psh[4 * 128];

    const int h     = blockIdx.y;
    const int warp  = threadIdx.x >> 5;
    const int lane  = threadIdx.x & 31;
    const int q0blk = blockIdx.x << 4;

    const float* Kb = g_K + (size_t)h * TSEQ * DHEAD;
    const float* Vb = g_vu + (size_t)h * DHEAD;      /* row stride 2048 */
    const float* Qb = g_Q + (size_t)h * TSEQ * DHEAD;

    {
        const int r  = threadIdx.x & 15;
        const int d4 = (threadIdx.x >> 4) << 2;
        for (int dd = d4; dd < 128; dd += 32) {
            float4 q4 = *(const float4*)(Qb + (size_t)(q0blk + r) * DHEAD + dd);
            qsT[(dd + 0) * 16 + r] = q4.x;
            qsT[(dd + 1) * 16 + r] = q4.y;
            qsT[(dd + 2) * 16 + r] = q4.z;
            qsT[(dd + 3) * 16 + r] = q4.w;
        }
    }

    float  m[4], l[4];
    float4 acc[4];
#pragma unroll
    for (int r = 0; r < 4; r++) {
        m[r] = -1e30f; l[r] = 0.f;
        acc[r] = make_float4(0.f, 0.f, 0.f, 0.f);
    }

    const int qbase  = q0blk + (warp << 2);
    const int ntiles = (q0blk + 15) / 32 + 1;

    for (int tile = 0; tile < ntiles; tile++) {
        const int kb = tile << 5;
        __syncthreads();
#pragma unroll
        for (int kk = warp; kk < 32; kk += 4) {
            const int d0 = lane << 2;
            float4 k4 = *(const float4*)(Kb + (size_t)(kb + kk) * DHEAD + d0);
            kT[(d0 + 0) * 36 + kk] = k4.x;
            kT[(d0 + 1) * 36 + kk] = k4.y;
            kT[(d0 + 2) * 36 + kk] = k4.z;
            kT[(d0 + 3) * 36 + kk] = k4.w;
            *(float4*)(&vs[kk * 128 + d0]) =
                *(const float4*)(Vb + (size_t)(kb + kk) * DMODEL + d0);
        }
        __syncthreads();

        float s[4] = {0.f, 0.f, 0.f, 0.f};
#pragma unroll 16
        for (int d = 0; d < 128; d++) {
            const float  kv = kT[d * 36 + lane];
            const float4 q4 = *(const float4*)(&qsT[d * 16 + (warp << 2)]);
            s[0] += kv * q4.x;
            s[1] += kv * q4.y;
            s[2] += kv * q4.z;
            s[3] += kv * q4.w;
        }

        const int key = kb + lane;
        float p[4];
#pragma unroll
        for (int r = 0; r < 4; r++) {
            float sv = s[r] * SCALE_ATT;
            if (key > qbase + r) sv = -1e30f;
            float mc = sv;
#pragma unroll
            for (int o = 16; o; o >>= 1)
                mc = fmaxf(mc, __shfl_xor_sync(0xffffffffu, mc, o));
            const float mn    = fmaxf(m[r], mc);
            const float alpha = __expf(m[r] - mn);
            const float pv    = __expf(sv - mn);
            float ps = pv;
#pragma unroll
            for (int o = 16; o; o >>= 1)
                ps += __shfl_xor_sync(0xffffffffu, ps, o);
            l[r] = l[r] * alpha + ps;
            acc[r].x *= alpha; acc[r].y *= alpha;
            acc[r].z *= alpha; acc[r].w *= alpha;
            m[r] = mn;
            p[r] = pv;
        }

        *(float4*)(&psh[warp * 128 + (lane << 2)]) =
            make_float4(p[0], p[1], p[2], p[3]);
        __syncwarp();

#pragma unroll 8
        for (int j = 0; j < 32; j++) {
            const float4 pj = *(const float4*)(&psh[warp * 128 + (j << 2)]);
            const float4 v4 = *(const float4*)(&vs[j * 128 + (lane << 2)]);
            acc[0].x += pj.x * v4.x; acc[0].y += pj.x * v4.y;
            acc[0].z += pj.x * v4.z; acc[0].w += pj.x * v4.w;
            acc[1].x += pj.y * v4.x; acc[1].y += pj.y * v4.y;
            acc[1].z += pj.y * v4.z; acc[1].w += pj.y * v4.w;
            acc[2].x += pj.z * v4.x; acc[2].y += pj.z * v4.y;
            acc[2].z += pj.z * v4.z; acc[2].w += pj.z * v4.w;
            acc[3].x += pj.w * v4.x; acc[3].y += pj.w * v4.y;
            acc[3].z += pj.w * v4.z; acc[3].w += pj.w * v4.w;
        }
        __syncwarp();
    }

#pragma unroll
    for (int r = 0; r < 4; r++) {
        const float inv = 1.0f / l[r];
        const float v0 = acc[r].x * inv, v1 = acc[r].y * inv;
        const float v2 = acc[r].z * inv, v3 = acc[r].w * inv;
        const float h0 = __bfloat162float(__float2bfloat16_rn(v0));
        const float h1 = __bfloat162float(__float2bfloat16_rn(v1));
        const float h2 = __bfloat162float(__float2bfloat16_rn(v2));
        const float h3 = __bfloat162float(__float2bfloat16_rn(v3));
        const size_t idx = (size_t)(qbase + r) * DMODEL + h * DHEAD + (lane << 2);
        uint2 hp, lp;
        hp.x = bf2pack(v0, v1);           hp.y = bf2pack(v2, v3);
        lp.x = bf2pack(v0 - h0, v1 - h1); lp.y = bf2pack(v2 - h2, v3 - h3);
        *(uint2*)(g_Oh + idx) = hp;
        *(uint2*)(g_Ol + idx) = lp;
    }
}

/* ------------------------------------------------------------------ */
extern "C" void kernel_launch(void* const* d_in, const int* in_sizes, int n_in,
                              void* d_out, int out_size)
{
    const float* x        = (const float*)d_in[0];
    const float* Wq_down  = (const float*)d_in[1];
    const float* Wq_up    = (const float*)d_in[2];
    const float* Wq_rope  = (const float*)d_in[3];
    const float* Wkv_down = (const float*)d_in[4];
    const float* Wk_up    = (const float*)d_in[5];
    const float* Wv_up    = (const float*)d_in[6];
    const float* Wk_rope  = (const float*)d_in[7];
    const float* Wo       = (const float*)d_in[8];
    float* out = (float*)d_out;

    float *qc, *qr, *kc, *kr, *vu;
    cudaGetSymbolAddress((void**)&qc, g_qc);
    cudaGetSymbolAddress((void**)&qr, g_qr);
    cudaGetSymbolAddress((void**)&kc, g_kc);
    cudaGetSymbolAddress((void**)&kr, g_kr);
    cudaGetSymbolAddress((void**)&vu, g_vu);

    __nv_bfloat16 *xh, *xl, *qdh, *qdl, *kvh, *kvl, *Oh, *Ol;
    __nv_bfloat16 *wqdh, *wqdl, *wquh, *wqul, *wqrh, *wqrl, *wkdh, *wkdl;
    __nv_bfloat16 *wkuh, *wkul, *wvuh, *wvul, *wkrh, *wkrl, *woh, *wol;
    cudaGetSymbolAddress((void**)&xh, g_xh);   cudaGetSymbolAddress((void**)&xl, g_xl);
    cudaGetSymbolAddress((void**)&qdh, g_qdh); cudaGetSymbolAddress((void**)&qdl, g_qdl);
    cudaGetSymbolAddress((void**)&kvh, g_kvh); cudaGetSymbolAddress((void**)&kvl, g_kvl);
    cudaGetSymbolAddress((void**)&Oh, g_Oh);   cudaGetSymbolAddress((void**)&Ol, g_Ol);
    cudaGetSymbolAddress((void**)&wqdh, g_wqdh); cudaGetSymbolAddress((void**)&wqdl, g_wqdl);
    cudaGetSymbolAddress((void**)&wquh, g_wquh); cudaGetSymbolAddress((void**)&wqul, g_wqul);
    cudaGetSymbolAddress((void**)&wqrh, g_wqrh); cudaGetSymbolAddress((void**)&wqrl, g_wqrl);
    cudaGetSymbolAddress((void**)&wkdh, g_wkdh); cudaGetSymbolAddress((void**)&wkdl, g_wkdl);
    cudaGetSymbolAddress((void**)&wkuh, g_wkuh); cudaGetSymbolAddress((void**)&wkul, g_wkul);
    cudaGetSymbolAddress((void**)&wvuh, g_wvuh); cudaGetSymbolAddress((void**)&wvul, g_wvul);
    cudaGetSymbolAddress((void**)&wkrh, g_wkrh); cudaGetSymbolAddress((void**)&wkrl, g_wkrl);
    cudaGetSymbolAddress((void**)&woh, g_woh);   cudaGetSymbolAddress((void**)&wol, g_wol);

    cudaFuncSetAttribute(gemm_fused,
                         cudaFuncAttributeMaxDynamicSharedMemorySize, 65536);

    /* 0. rope table (fp64 once) */
    rope_table<<<256, 256>>>();

    /* 1. split inputs + weights to bf16 hi/lo */
    SplitJobs js;
    js.j[0] = { x,        xh,   xl,   TSEQ * 2048 };
    js.j[1] = { Wq_down,  wqdh, wqdl, 2048 * 512  };
    js.j[2] = { Wq_up,    wquh, wqul, 512 * 1024  };
    js.j[3] = { Wq_rope,  wqrh, wqrl, 2048 * 1024 };
    js.j[4] = { Wkv_down, wkdh, wkdl, 2048 * 512  };
    js.j[5] = { Wk_up,    wkuh, wkul, 512 * 1024  };
    js.j[6] = { Wv_up,    wvuh, wvul, 512 * 2048  };
    js.j[7] = { Wk_rope,  wkrh, wkrl, 2048 * 1024 };
    js.j[8] = { Wo,       woh,  wol,  2048 * 2048 };
    split_many<<<dim3(4096, 9), 256>>>(js);

    /* 2. GEMM1: x @ [Wq_down | Wkv_down | Wq_rope | Wk_rope] */
    {
        GSegs g; g.n = 4;
        g.s[0] = { xh, xl, 2048, wqdh, wqdl, nullptr, qdh, qdl,  512, 2048, 0  };
        g.s[1] = { xh, xl, 2048, wkdh, wkdl, nullptr, kvh, kvl,  512, 2048, 4  };
        g.s[2] = { xh, xl, 2048, wqrh, wqrl, qr, nullptr, nullptr, 1024, 2048, 8  };
        g.s[3] = { xh, xl, 2048, wkrh, wkrl, kr, nullptr, nullptr, 1024, 2048, 16 };
        gemm_fused<<<dim3(24, 16), 256, 65536>>>(g);
    }

    /* 3. GEMM2: qd @ Wq_up ; kv @ [Wk_up | Wv_up] */
    {
        GSegs g; g.n = 3;
        g.s[0] = { qdh, qdl, 512, wquh, wqul, qc, nullptr, nullptr, 1024, 512, 0  };
        g.s[1] = { kvh, kvl, 512, wkuh, wkul, kc, nullptr, nullptr, 1024, 512, 8  };
        g.s[2] = { kvh, kvl, 512, wvuh, wvul, vu, nullptr, nullptr, 2048, 512, 16 };
        g.s[3] = g.s[0];
        gemm_fused<<<dim3(32, 16), 256, 65536>>>(g);
    }

    /* 4. rope + layout (Q/K only; V read in-place by attention) */
    pack_kernel<<<dim3(TSEQ, NH), 128>>>();

    /* 5. causal attention (writes O as bf16 hi/lo) */
    attn_kernel<<<dim3(TSEQ / 16, NH), 128>>>();

    /* 6. GEMM3: O @ Wo -> out */
    {
        GSegs g; g.n = 1;
        g.s[0] = { Oh, Ol, 2048, woh, wol, out, nullptr, nullptr, 2048, 2048, 0 };
        g.s[1] = g.s[0]; g.s[2] = g.s[0]; g.s[3] = g.s[0];
        gemm_fused<<<dim3(16, 16), 256, 65536>>>(g);
    }
}

// round 6
// speedup vs baseline: 4.5781x; 2.5864x over previous
#include <cuda_runtime.h>
#include <cuda_bf16.h>
#include <math.h>
#include <stdint.h>

#define TSEQ   2048
#define DMODEL 2048
#define NH     16
#define DHEAD  128
#define DROPE  64
#define DCONT  64
#define SCALE_ATT 0.08838834764831845f  /* 1/sqrt(128) */

/* ------------------------------------------------------------------ */
/* Scratch (device globals)                                            */
/* ------------------------------------------------------------------ */
__device__ float g_qc[TSEQ * 1024];
__device__ float g_qr[TSEQ * 1024];
__device__ float g_kc[TSEQ * 1024];
__device__ float g_kr[TSEQ * 1024];
__device__ float g_cosT[TSEQ * 32];
__device__ float g_sinT[TSEQ * 32];

/* attention operands, bf16 hi/lo, [h][t][d] */
__device__ __nv_bfloat16 g_Qh[NH * TSEQ * DHEAD], g_Ql[NH * TSEQ * DHEAD];
__device__ __nv_bfloat16 g_Kh[NH * TSEQ * DHEAD], g_Kl[NH * TSEQ * DHEAD];
__device__ __nv_bfloat16 g_Vh[NH * TSEQ * DHEAD], g_Vl[NH * TSEQ * DHEAD];

/* bf16 hi/lo split operands for GEMMs */
__device__ __nv_bfloat16 g_xh[TSEQ * 2048],  g_xl[TSEQ * 2048];
__device__ __nv_bfloat16 g_qdh[TSEQ * 512],  g_qdl[TSEQ * 512];
__device__ __nv_bfloat16 g_kvh[TSEQ * 512],  g_kvl[TSEQ * 512];
__device__ __nv_bfloat16 g_Oh[TSEQ * 2048],  g_Ol[TSEQ * 2048];
__device__ __nv_bfloat16 g_wqdh[2048 * 512], g_wqdl[2048 * 512];
__device__ __nv_bfloat16 g_wquh[512 * 1024], g_wqul[512 * 1024];
__device__ __nv_bfloat16 g_wqrh[2048 * 1024],g_wqrl[2048 * 1024];
__device__ __nv_bfloat16 g_wkdh[2048 * 512], g_wkdl[2048 * 512];
__device__ __nv_bfloat16 g_wkuh[512 * 1024], g_wkul[512 * 1024];
__device__ __nv_bfloat16 g_wvuh[512 * 2048], g_wvul[512 * 2048];
__device__ __nv_bfloat16 g_wkrh[2048 * 1024],g_wkrl[2048 * 1024];
__device__ __nv_bfloat16 g_woh[2048 * 2048], g_wol[2048 * 2048];

/* ------------------------------------------------------------------ */
/* asm helpers                                                         */
/* ------------------------------------------------------------------ */
#define CPA16(dst, src)                                                    \
    asm volatile("cp.async.cg.shared.global [%0], [%1], 16;"               \
                 :: "r"(dst), "l"(src))
#define CPA_COMMIT() asm volatile("cp.async.commit_group;")
#define CPA_WAIT1()  asm volatile("cp.async.wait_group 1;")
#define CPA_WAIT0()  asm volatile("cp.async.wait_group 0;")

#define LDSM4(r0, r1, r2, r3, addr)                                        \
    asm volatile("ldmatrix.sync.aligned.m8n8.x4.shared.b16 {%0,%1,%2,%3}, [%4];" \
                 : "=r"(r0), "=r"(r1), "=r"(r2), "=r"(r3) : "r"(addr))
#define LDSM4T(r0, r1, r2, r3, addr)                                       \
    asm volatile("ldmatrix.sync.aligned.m8n8.x4.trans.shared.b16 {%0,%1,%2,%3}, [%4];" \
                 : "=r"(r0), "=r"(r1), "=r"(r2), "=r"(r3) : "r"(addr))
#define MMA_BF16(c, a, b0, b1)                                             \
    asm volatile("mma.sync.aligned.m16n8k16.row.col.f32.bf16.bf16.f32 "    \
                 "{%0,%1,%2,%3}, {%4,%5,%6,%7}, {%8,%9}, {%0,%1,%2,%3};"   \
                 : "+f"(c[0]), "+f"(c[1]), "+f"(c[2]), "+f"(c[3])          \
                 : "r"(a[0]), "r"(a[1]), "r"(a[2]), "r"(a[3]),             \
                   "r"(b0), "r"(b1))

__device__ __forceinline__ uint32_t bf2pack(float a, float b)
{
    return (uint32_t)__bfloat16_as_ushort(__float2bfloat16_rn(a)) |
           ((uint32_t)__bfloat16_as_ushort(__float2bfloat16_rn(b)) << 16);
}

/* ------------------------------------------------------------------ */
/* RoPE table                                                          */
/* ------------------------------------------------------------------ */
__global__ void __launch_bounds__(256) rope_table()
{
    const int idx = blockIdx.x * 256 + threadIdx.x;
    if (idx >= TSEQ * 32) return;
    const int t = idx >> 5, i = idx & 31;
    const double inv = pow(10000.0, -(double)i / 32.0);
    double sd, cd;
    sincos((double)t * inv, &sd, &cd);
    g_cosT[idx] = (float)cd;
    g_sinT[idx] = (float)sd;
}

/* ------------------------------------------------------------------ */
/* Batched fp32 -> bf16 hi/lo split                                    */
/* ------------------------------------------------------------------ */
struct SplitJob { const float* src; __nv_bfloat16 *h, *l; int n; };
struct SplitJobs { SplitJob j[9]; };

__global__ void __launch_bounds__(256) split_many(SplitJobs js)
{
    const SplitJob J = js.j[blockIdx.y];
    const int i = (blockIdx.x * 256 + threadIdx.x) << 2;
    if (i >= J.n) return;
    float4 v = *(const float4*)(J.src + i);
    float h0 = __bfloat162float(__float2bfloat16_rn(v.x));
    float h1 = __bfloat162float(__float2bfloat16_rn(v.y));
    float h2 = __bfloat162float(__float2bfloat16_rn(v.z));
    float h3 = __bfloat162float(__float2bfloat16_rn(v.w));
    uint2 hp, lp;
    hp.x = bf2pack(v.x, v.y);          hp.y = bf2pack(v.z, v.w);
    lp.x = bf2pack(v.x - h0, v.y - h1); lp.y = bf2pack(v.z - h2, v.w - h3);
    *(uint2*)(J.h + i) = hp;
    *(uint2*)(J.l + i) = lp;
}

/* ------------------------------------------------------------------ */
/* Fused multi-segment split-bf16 tensor-core GEMM                     */
/* ------------------------------------------------------------------ */
struct GSeg {
    const __nv_bfloat16 *Ah, *Al;
    int lda;
    const __nv_bfloat16 *Bh, *Bl;
    float* Cf;
    __nv_bfloat16 *Ch, *Cl;
    int N, K, tile0, vperm;
};
struct GSegs { GSeg s[4]; int n; };

#define STAGE_BYTES 32768
#define A_LO_OFF    8192
#define B_HI_OFF    16384
#define B_LO_OFF    24576

__device__ __forceinline__ uint32_t offA(int r, int c)
{ return (uint32_t)(((r << 2) + (c ^ ((r >> 1) & 3))) << 4); }
__device__ __forceinline__ uint32_t offB(int r, int c)
{ return (uint32_t)(((r << 4) + (c ^ (r & 7))) << 4); }

__global__ void __launch_bounds__(256) gemm_fused(GSegs segs)
{
    extern __shared__ char dsm[];
    const uint32_t sb = (uint32_t)__cvta_generic_to_shared(dsm);

    const int tid  = threadIdx.x;
    const int lane = tid & 31;
    const int warp = tid >> 5;
    const int wm   = (warp >> 1) << 5;
    const int wn   = (warp & 1) << 6;
    const int bm   = blockIdx.y << 7;

    GSeg sg = segs.s[0];
#pragma unroll
    for (int i = 1; i < 4; i++)
        if (i < segs.n && (int)blockIdx.x >= segs.s[i].tile0) sg = segs.s[i];
    const int bn  = ((int)blockIdx.x - sg.tile0) << 7;
    const int lda = sg.lda, ldb = sg.N, K = sg.K;

    const int ar = tid >> 2, ac = tid & 3;
    const int br = tid >> 3, bc = tid & 7;
    const uint32_t aoff0 = offA(ar, ac), aoff1 = offA(ar + 64, ac);
    const uint32_t boff0 = offB(br, bc), boff1 = offB(br, bc + 8);

    const __nv_bfloat16* gAh = sg.Ah + (size_t)(bm + ar) * lda + ac * 8;
    const __nv_bfloat16* gAl = sg.Al + (size_t)(bm + ar) * lda + ac * 8;
    const __nv_bfloat16* gBh = sg.Bh + (size_t)br * ldb + bn + bc * 8;
    const __nv_bfloat16* gBl = sg.Bl + (size_t)br * ldb + bn + bc * 8;

    float acc[2][8][4];
#pragma unroll
    for (int mt = 0; mt < 2; mt++)
#pragma unroll
        for (int nt = 0; nt < 8; nt++)
#pragma unroll
            for (int i = 0; i < 4; i++) acc[mt][nt][i] = 0.f;

    const int nk = K >> 5;

    auto load_stage = [&](int st, int k0) {
        const uint32_t s0 = sb + st * STAGE_BYTES;
        const __nv_bfloat16* pAh = gAh + k0;
        const __nv_bfloat16* pAl = gAl + k0;
        CPA16(s0 + aoff0, pAh);
        CPA16(s0 + aoff1, pAh + (size_t)64 * lda);
        CPA16(s0 + A_LO_OFF + aoff0, pAl);
        CPA16(s0 + A_LO_OFF + aoff1, pAl + (size_t)64 * lda);
        const __nv_bfloat16* pBh = gBh + (size_t)k0 * ldb;
        const __nv_bfloat16* pBl = gBl + (size_t)k0 * ldb;
        CPA16(s0 + B_HI_OFF + boff0, pBh);
        CPA16(s0 + B_HI_OFF + boff1, pBh + 64);
        CPA16(s0 + B_LO_OFF + boff0, pBl);
        CPA16(s0 + B_LO_OFF + boff1, pBl + 64);
    };

    load_stage(0, 0);
    CPA_COMMIT();

    for (int it = 0; it < nk; it++) {
        if (it + 1 < nk) { load_stage((it + 1) & 1, (it + 1) << 5); CPA_COMMIT(); }
        if (it + 1 < nk) CPA_WAIT1(); else CPA_WAIT0();
        __syncthreads();

        const uint32_t s0 = sb + (it & 1) * STAGE_BYTES;
#pragma unroll
        for (int ks = 0; ks < 2; ks++) {
            uint32_t ah[2][4], al_[2][4];
#pragma unroll
            for (int mt = 0; mt < 2; mt++) {
                const int rowA   = wm + (mt << 4) + (lane & 15);
                const int chunkA = (ks << 1) + (lane >> 4);
                const uint32_t ad = s0 + offA(rowA, chunkA);
                LDSM4(ah[mt][0], ah[mt][1], ah[mt][2], ah[mt][3], ad);
                LDSM4(al_[mt][0], al_[mt][1], al_[mt][2], al_[mt][3], ad + A_LO_OFF);
            }
            uint32_t bhf[8][2], blf[8][2];
#pragma unroll
            for (int np = 0; np < 4; np++) {
                const int rowB   = (ks << 4) + (lane & 15);
                const int chunkB = (wn >> 3) + (lane >> 4) + (np << 1);
                const uint32_t bd = s0 + B_HI_OFF + offB(rowB, chunkB);
                uint32_t r0, r1, r2, r3;
                LDSM4T(r0, r1, r2, r3, bd);
                bhf[2 * np][0] = r0; bhf[2 * np][1] = r1;
                bhf[2 * np + 1][0] = r2; bhf[2 * np + 1][1] = r3;
                LDSM4T(r0, r1, r2, r3, bd + 8192);
                blf[2 * np][0] = r0; blf[2 * np][1] = r1;
                blf[2 * np + 1][0] = r2; blf[2 * np + 1][1] = r3;
            }
#pragma unroll
            for (int mt = 0; mt < 2; mt++)
#pragma unroll
                for (int nt = 0; nt < 8; nt++) {
                    MMA_BF16(acc[mt][nt], ah[mt],  bhf[nt][0], bhf[nt][1]);
                    MMA_BF16(acc[mt][nt], ah[mt],  blf[nt][0], blf[nt][1]);
                    MMA_BF16(acc[mt][nt], al_[mt], bhf[nt][0], bhf[nt][1]);
                }
        }
        __syncthreads();
    }

    const int erow = lane >> 2;
    const int ecol = (lane & 3) << 1;
    if (sg.Cf) {
#pragma unroll
        for (int mt = 0; mt < 2; mt++)
#pragma unroll
            for (int nt = 0; nt < 8; nt++) {
                const int r = bm + wm + (mt << 4) + erow;
                const int c = bn + wn + (nt << 3) + ecol;
                *(float2*)(sg.Cf + (size_t)r * ldb + c) =
                    make_float2(acc[mt][nt][0], acc[mt][nt][1]);
                *(float2*)(sg.Cf + (size_t)(r + 8) * ldb + c) =
                    make_float2(acc[mt][nt][2], acc[mt][nt][3]);
            }
    } else {
#pragma unroll
        for (int mt = 0; mt < 2; mt++)
#pragma unroll
            for (int nt = 0; nt < 8; nt++) {
                const int r = bm + wm + (mt << 4) + erow;
                const int c = bn + wn + (nt << 3) + ecol;
#pragma unroll
                for (int hh = 0; hh < 2; hh++) {
                    const float v0 = acc[mt][nt][2 * hh];
                    const float v1 = acc[mt][nt][2 * hh + 1];
                    const float h0 = __bfloat162float(__float2bfloat16_rn(v0));
                    const float h1 = __bfloat162float(__float2bfloat16_rn(v1));
                    const int rr = r + 8 * hh;
                    size_t idx;
                    if (sg.vperm)
                        idx = ((size_t)(c >> 7) * TSEQ + rr) * DHEAD + (c & 127);
                    else
                        idx = (size_t)rr * ldb + c;
                    *(uint32_t*)(sg.Ch + idx) = bf2pack(v0, v1);
                    *(uint32_t*)(sg.Cl + idx) = bf2pack(v0 - h0, v1 - h1);
                }
            }
    }
}

/* ------------------------------------------------------------------ */
/* Pack + RoPE -> Qh/Ql (pre-scaled), Kh/Kl in [h][t][d].              */
/* ------------------------------------------------------------------ */
__global__ void __launch_bounds__(64) pack_kernel()
{
    const int t = blockIdx.x;
    const int h = blockIdx.y;
    const int d2 = threadIdx.x << 1;
    const size_t o = ((size_t)h * TSEQ + t) * DHEAD + d2;

    float q0, q1, k0, k1;
    if (d2 < DCONT) {
        const size_t b = (size_t)t * 1024 + h * DCONT + d2;
        q0 = g_qc[b];     q1 = g_qc[b + 1];
        k0 = g_kc[b];     k1 = g_kc[b + 1];
    } else {
        const int i = d2 - DCONT;
        const int ip = (i < 32) ? i : i - 32;
        const float c0 = g_cosT[t * 32 + ip],     s0 = g_sinT[t * 32 + ip];
        const float c1 = g_cosT[t * 32 + ip + 1], s1 = g_sinT[t * 32 + ip + 1];
        const size_t b = (size_t)t * 1024 + h * DROPE;
        const float qa0 = g_qr[b + ip],      qa1 = g_qr[b + ip + 1];
        const float qb0 = g_qr[b + 32 + ip], qb1 = g_qr[b + 32 + ip + 1];
        const float ka0 = g_kr[b + ip],      ka1 = g_kr[b + ip + 1];
        const float kb0 = g_kr[b + 32 + ip], kb1 = g_kr[b + 32 + ip + 1];
        if (i < 32) {
            q0 = qa0 * c0 - qb0 * s0;  q1 = qa1 * c1 - qb1 * s1;
            k0 = ka0 * c0 - kb0 * s0;  k1 = ka1 * c1 - kb1 * s1;
        } else {
            q0 = qa0 * s0 + qb0 * c0;  q1 = qa1 * s1 + qb1 * c1;
            k0 = ka0 * s0 + kb0 * c0;  k1 = ka1 * s1 + kb1 * c1;
        }
    }
    q0 *= SCALE_ATT; q1 *= SCALE_ATT;

    const float qh0 = __bfloat162float(__float2bfloat16_rn(q0));
    const float qh1 = __bfloat162float(__float2bfloat16_rn(q1));
    const float kh0 = __bfloat162float(__float2bfloat16_rn(k0));
    const float kh1 = __bfloat162float(__float2bfloat16_rn(k1));
    *(uint32_t*)(g_Qh + o) = bf2pack(q0, q1);
    *(uint32_t*)(g_Ql + o) = bf2pack(q0 - qh0, q1 - qh1);
    *(uint32_t*)(g_Kh + o) = bf2pack(k0, k1);
    *(uint32_t*)(g_Kl + o) = bf2pack(k0 - kh0, k1 - kh1);
}

/* ------------------------------------------------------------------ */
/* Tensor-core causal flash attention (split bf16).                    */
/* CTA: 64 q-rows x 1 head. 4 warps x 16 rows. k-tiles of 64. d=128.  */
/* smem: Kh | Kl | Vh | Vl, each 64 rows x 16 chunks(16B) swizzled.    */
/* ------------------------------------------------------------------ */
__device__ __forceinline__ uint32_t offV(int r, int c)
{ return (uint32_t)(((r << 4) + (c ^ (r & 7))) << 4); }   /* 16 chunks/row */

#define SM_KH 0
#define SM_KL 16384
#define SM_VH 32768
#define SM_VL 49152

__global__ void __launch_bounds__(128) attn_mma()
{
    extern __shared__ char dsm[];
    const uint32_t sb = (uint32_t)__cvta_generic_to_shared(dsm);

    const int h    = blockIdx.y;
    const int qblk = 31 - (int)blockIdx.x;       /* long CTAs first */
    const int qb   = qblk << 6;
    const int tid  = threadIdx.x;
    const int lane = tid & 31;
    const int warp = tid >> 5;
    const int w16  = warp << 4;

    const __nv_bfloat16* Qhb = g_Qh + (size_t)h * TSEQ * DHEAD;
    const __nv_bfloat16* Qlb = g_Ql + (size_t)h * TSEQ * DHEAD;
    const __nv_bfloat16* Khb = g_Kh + (size_t)h * TSEQ * DHEAD;
    const __nv_bfloat16* Klb = g_Kl + (size_t)h * TSEQ * DHEAD;
    const __nv_bfloat16* Vhb = g_Vh + (size_t)h * TSEQ * DHEAD;
    const __nv_bfloat16* Vlb = g_Vl + (size_t)h * TSEQ * DHEAD;

    /* staging geometry: 64 rows x 16 chunks; 128 threads -> 8 rows/pass */
    const int sr = tid >> 4;            /* 0..7  */
    const int sc = tid & 15;            /* 0..15 */

    /* ---- stage Q (64 rows) into KH/KL, LDSM into regs ---- */
#pragma unroll
    for (int p = 0; p < 8; p++) {
        const int r = sr + (p << 3);
        CPA16(sb + SM_KH + offV(r, sc), Qhb + (size_t)(qb + r) * DHEAD + sc * 8);
        CPA16(sb + SM_KL + offV(r, sc), Qlb + (size_t)(qb + r) * DHEAD + sc * 8);
    }
    CPA_COMMIT(); CPA_WAIT0();
    __syncthreads();

    uint32_t qh[8][4], ql[8][4];
#pragma unroll
    for (int ks = 0; ks < 8; ks++) {
        const uint32_t ad = offV(w16 + (lane & 15), (ks << 1) + (lane >> 4));
        LDSM4(qh[ks][0], qh[ks][1], qh[ks][2], qh[ks][3], sb + SM_KH + ad);
        LDSM4(ql[ks][0], ql[ks][1], ql[ks][2], ql[ks][3], sb + SM_KL + ad);
    }
    __syncthreads();

    float O[16][4];
#pragma unroll
    for (int nt = 0; nt < 16; nt++)
#pragma unroll
        for (int i = 0; i < 4; i++) O[nt][i] = 0.f;
    float m0 = -1e30f, m1 = -1e30f, l0 = 0.f, l1 = 0.f;

    const int ntiles = qblk + 1;
    const int row0 = qb + w16 + (lane >> 2);
    const int row1 = row0 + 8;

    for (int kt = 0; kt < ntiles; kt++) {
        const int kb = kt << 6;

        /* stage K/V tiles (hi+lo) */
#pragma unroll
        for (int p = 0; p < 8; p++) {
            const int r = sr + (p << 3);
            const size_t gi = (size_t)(kb + r) * DHEAD + sc * 8;
            const uint32_t so = offV(r, sc);
            CPA16(sb + SM_KH + so, Khb + gi);
            CPA16(sb + SM_KL + so, Klb + gi);
            CPA16(sb + SM_VH + so, Vhb + gi);
            CPA16(sb + SM_VL + so, Vlb + gi);
        }
        CPA_COMMIT(); CPA_WAIT0();
        __syncthreads();

        /* ---- scores S = Q K^T (16 x 64 per warp) ---- */
        float S[8][4];
#pragma unroll
        for (int nt = 0; nt < 8; nt++)
#pragma unroll
            for (int i = 0; i < 4; i++) S[nt][i] = 0.f;

#pragma unroll
        for (int ntp = 0; ntp < 4; ntp++) {
#pragma unroll
            for (int ks = 0; ks < 8; ks++) {
                const uint32_t ad = offV((ntp << 4) + (lane & 15),
                                         (ks << 1) + (lane >> 4));
                uint32_t kh0, kh1, kh2, kh3, kl0, kl1, kl2, kl3;
                LDSM4(kh0, kh1, kh2, kh3, sb + SM_KH + ad);
                LDSM4(kl0, kl1, kl2, kl3, sb + SM_KL + ad);
                MMA_BF16(S[2 * ntp],     qh[ks], kh0, kh2);
                MMA_BF16(S[2 * ntp],     qh[ks], kl0, kl2);
                MMA_BF16(S[2 * ntp],     ql[ks], kh0, kh2);
                MMA_BF16(S[2 * ntp + 1], qh[ks], kh1, kh3);
                MMA_BF16(S[2 * ntp + 1], qh[ks], kl1, kl3);
                MMA_BF16(S[2 * ntp + 1], ql[ks], kh1, kh3);
            }
        }

        /* ---- causal mask on diagonal tile ---- */
        if (kb == qb) {
#pragma unroll
            for (int nt = 0; nt < 8; nt++) {
                const int key = kb + (nt << 3) + ((lane & 3) << 1);
                if (key > row0)     S[nt][0] = -1e30f;
                if (key + 1 > row0) S[nt][1] = -1e30f;
                if (key > row1)     S[nt][2] = -1e30f;
                if (key + 1 > row1) S[nt][3] = -1e30f;
            }
        }

        /* ---- online softmax ---- */
        float mx0 = -1e30f, mx1 = -1e30f;
#pragma unroll
        for (int nt = 0; nt < 8; nt++) {
            mx0 = fmaxf(mx0, fmaxf(S[nt][0], S[nt][1]));
            mx1 = fmaxf(mx1, fmaxf(S[nt][2], S[nt][3]));
        }
        mx0 = fmaxf(mx0, __shfl_xor_sync(0xffffffffu, mx0, 1));
        mx0 = fmaxf(mx0, __shfl_xor_sync(0xffffffffu, mx0, 2));
        mx1 = fmaxf(mx1, __shfl_xor_sync(0xffffffffu, mx1, 1));
        mx1 = fmaxf(mx1, __shfl_xor_sync(0xffffffffu, mx1, 2));

        const float m0n = fmaxf(m0, mx0), m1n = fmaxf(m1, mx1);
        const float a0 = __expf(m0 - m0n), a1 = __expf(m1 - m1n);
        m0 = m0n; m1 = m1n;

        uint32_t aH[4][4], aL[4][4];
        float ps0 = 0.f, ps1 = 0.f;
#pragma unroll
        for (int nt = 0; nt < 8; nt++) {
            const float p0 = __expf(S[nt][0] - m0n);
            const float p1 = __expf(S[nt][1] - m0n);
            const float p2 = __expf(S[nt][2] - m1n);
            const float p3 = __expf(S[nt][3] - m1n);
            ps0 += p0 + p1; ps1 += p2 + p3;
            const float h0 = __bfloat162float(__float2bfloat16_rn(p0));
            const float h1 = __bfloat162float(__float2bfloat16_rn(p1));
            const float h2 = __bfloat162float(__float2bfloat16_rn(p2));
            const float h3 = __bfloat162float(__float2bfloat16_rn(p3));
            const int kk = nt >> 1;
            const int e  = (nt & 1) << 1;
            aH[kk][e]     = bf2pack(p0, p1);
            aH[kk][e + 1] = bf2pack(p2, p3);
            aL[kk][e]     = bf2pack(p0 - h0, p1 - h1);
            aL[kk][e + 1] = bf2pack(p2 - h2, p3 - h3);
        }
        ps0 += __shfl_xor_sync(0xffffffffu, ps0, 1);
        ps0 += __shfl_xor_sync(0xffffffffu, ps0, 2);
        ps1 += __shfl_xor_sync(0xffffffffu, ps1, 1);
        ps1 += __shfl_xor_sync(0xffffffffu, ps1, 2);
        l0 = l0 * a0 + ps0;
        l1 = l1 * a1 + ps1;

#pragma unroll
        for (int nt = 0; nt < 16; nt++) {
            O[nt][0] *= a0; O[nt][1] *= a0;
            O[nt][2] *= a1; O[nt][3] *= a1;
        }

        /* ---- O += P V ---- */
#pragma unroll
        for (int kk = 0; kk < 4; kk++) {
#pragma unroll
            for (int ntp = 0; ntp < 8; ntp++) {
                const uint32_t ad = offV((kk << 4) + (lane & 15),
                                         (ntp << 1) + (lane >> 4));
                uint32_t vh0, vh1, vh2, vh3, vl0, vl1, vl2, vl3;
                LDSM4T(vh0, vh1, vh2, vh3, sb + SM_VH + ad);
                LDSM4T(vl0, vl1, vl2, vl3, sb + SM_VL + ad);
                MMA_BF16(O[2 * ntp],     aH[kk], vh0, vh1);
                MMA_BF16(O[2 * ntp],     aH[kk], vl0, vl1);
                MMA_BF16(O[2 * ntp],     aL[kk], vh0, vh1);
                MMA_BF16(O[2 * ntp + 1], aH[kk], vh2, vh3);
                MMA_BF16(O[2 * ntp + 1], aH[kk], vl2, vl3);
                MMA_BF16(O[2 * ntp + 1], aL[kk], vh2, vh3);
            }
        }
        __syncthreads();
    }

    /* ---- epilogue: normalize, write bf16 hi/lo [t][h*128+d] ---- */
    const float inv0 = 1.0f / l0, inv1 = 1.0f / l1;
#pragma unroll
    for (int nt = 0; nt < 16; nt++) {
        const int d = (nt << 3) + ((lane & 3) << 1);
        const float v0 = O[nt][0] * inv0, v1 = O[nt][1] * inv0;
        const float v2 = O[nt][2] * inv1, v3 = O[nt][3] * inv1;
        const float h0 = __bfloat162float(__float2bfloat16_rn(v0));
        const float h1 = __bfloat162float(__float2bfloat16_rn(v1));
        const float h2 = __bfloat162float(__float2bfloat16_rn(v2));
        const float h3 = __bfloat162float(__float2bfloat16_rn(v3));
        const size_t i0 = (size_t)row0 * DMODEL + h * DHEAD + d;
        const size_t i1 = (size_t)row1 * DMODEL + h * DHEAD + d;
        *(uint32_t*)(g_Oh + i0) = bf2pack(v0, v1);
        *(uint32_t*)(g_Ol + i0) = bf2pack(v0 - h0, v1 - h1);
        *(uint32_t*)(g_Oh + i1) = bf2pack(v2, v3);
        *(uint32_t*)(g_Ol + i1) = bf2pack(v2 - h2, v3 - h3);
    }
}

/* ------------------------------------------------------------------ */
extern "C" void kernel_launch(void* const* d_in, const int* in_sizes, int n_in,
                              void* d_out, int out_size)
{
    const float* x        = (const float*)d_in[0];
    const float* Wq_down  = (const float*)d_in[1];
    const float* Wq_up    = (const float*)d_in[2];
    const float* Wq_rope  = (const float*)d_in[3];
    const float* Wkv_down = (const float*)d_in[4];
    const float* Wk_up    = (const float*)d_in[5];
    const float* Wv_up    = (const float*)d_in[6];
    const float* Wk_rope  = (const float*)d_in[7];
    const float* Wo       = (const float*)d_in[8];
    float* out = (float*)d_out;

    float *qc, *qr, *kc, *kr;
    cudaGetSymbolAddress((void**)&qc, g_qc);
    cudaGetSymbolAddress((void**)&qr, g_qr);
    cudaGetSymbolAddress((void**)&kc, g_kc);
    cudaGetSymbolAddress((void**)&kr, g_kr);

    __nv_bfloat16 *xh, *xl, *qdh, *qdl, *kvh, *kvl, *Oh, *Ol, *Vh, *Vl;
    __nv_bfloat16 *wqdh, *wqdl, *wquh, *wqul, *wqrh, *wqrl, *wkdh, *wkdl;
    __nv_bfloat16 *wkuh, *wkul, *wvuh, *wvul, *wkrh, *wkrl, *woh, *wol;
    cudaGetSymbolAddress((void**)&xh, g_xh);   cudaGetSymbolAddress((void**)&xl, g_xl);
    cudaGetSymbolAddress((void**)&qdh, g_qdh); cudaGetSymbolAddress((void**)&qdl, g_qdl);
    cudaGetSymbolAddress((void**)&kvh, g_kvh); cudaGetSymbolAddress((void**)&kvl, g_kvl);
    cudaGetSymbolAddress((void**)&Oh, g_Oh);   cudaGetSymbolAddress((void**)&Ol, g_Ol);
    cudaGetSymbolAddress((void**)&Vh, g_Vh);   cudaGetSymbolAddress((void**)&Vl, g_Vl);
    cudaGetSymbolAddress((void**)&wqdh, g_wqdh); cudaGetSymbolAddress((void**)&wqdl, g_wqdl);
    cudaGetSymbolAddress((void**)&wquh, g_wquh); cudaGetSymbolAddress((void**)&wqul, g_wqul);
    cudaGetSymbolAddress((void**)&wqrh, g_wqrh); cudaGetSymbolAddress((void**)&wqrl, g_wqrl);
    cudaGetSymbolAddress((void**)&wkdh, g_wkdh); cudaGetSymbolAddress((void**)&wkdl, g_wkdl);
    cudaGetSymbolAddress((void**)&wkuh, g_wkuh); cudaGetSymbolAddress((void**)&wkul, g_wkul);
    cudaGetSymbolAddress((void**)&wvuh, g_wvuh); cudaGetSymbolAddress((void**)&wvul, g_wvul);
    cudaGetSymbolAddress((void**)&wkrh, g_wkrh); cudaGetSymbolAddress((void**)&wkrl, g_wkrl);
    cudaGetSymbolAddress((void**)&woh, g_woh);   cudaGetSymbolAddress((void**)&wol, g_wol);

    cudaFuncSetAttribute(gemm_fused,
                         cudaFuncAttributeMaxDynamicSharedMemorySize, 65536);
    cudaFuncSetAttribute(attn_mma,
                         cudaFuncAttributeMaxDynamicSharedMemorySize, 65536);

    /* 0. rope table */
    rope_table<<<256, 256>>>();

    /* 1. split inputs + weights */
    SplitJobs js;
    js.j[0] = { x,        xh,   xl,   TSEQ * 2048 };
    js.j[1] = { Wq_down,  wqdh, wqdl, 2048 * 512  };
    js.j[2] = { Wq_up,    wquh, wqul, 512 * 1024  };
    js.j[3] = { Wq_rope,  wqrh, wqrl, 2048 * 1024 };
    js.j[4] = { Wkv_down, wkdh, wkdl, 2048 * 512  };
    js.j[5] = { Wk_up,    wkuh, wkul, 512 * 1024  };
    js.j[6] = { Wv_up,    wvuh, wvul, 512 * 2048  };
    js.j[7] = { Wk_rope,  wkrh, wkrl, 2048 * 1024 };
    js.j[8] = { Wo,       woh,  wol,  2048 * 2048 };
    split_many<<<dim3(4096, 9), 256>>>(js);

    /* 2. GEMM1: x @ [Wq_down | Wkv_down | Wq_rope | Wk_rope] */
    {
        GSegs g; g.n = 4;
        g.s[0] = { xh, xl, 2048, wqdh, wqdl, nullptr, qdh, qdl,  512, 2048, 0,  0 };
        g.s[1] = { xh, xl, 2048, wkdh, wkdl, nullptr, kvh, kvl,  512, 2048, 4,  0 };
        g.s[2] = { xh, xl, 2048, wqrh, wqrl, qr, nullptr, nullptr, 1024, 2048, 8,  0 };
        g.s[3] = { xh, xl, 2048, wkrh, wkrl, kr, nullptr, nullptr, 1024, 2048, 16, 0 };
        gemm_fused<<<dim3(24, 16), 256, 65536>>>(g);
    }

    /* 3. GEMM2: qd @ Wq_up ; kv @ [Wk_up | Wv_up (-> Vh/Vl permuted)] */
    {
        GSegs g; g.n = 3;
        g.s[0] = { qdh, qdl, 512, wquh, wqul, qc, nullptr, nullptr, 1024, 512, 0,  0 };
        g.s[1] = { kvh, kvl, 512, wkuh, wkul, kc, nullptr, nullptr, 1024, 512, 8,  0 };
        g.s[2] = { kvh, kvl, 512, wvuh, wvul, nullptr, Vh, Vl,      2048, 512, 16, 1 };
        g.s[3] = g.s[0];
        gemm_fused<<<dim3(32, 16), 256, 65536>>>(g);
    }

    /* 4. rope + pack Q/K (bf16 hi/lo, pre-scaled Q) */
    pack_kernel<<<dim3(TSEQ, NH), 64>>>();

    /* 5. tensor-core causal attention */
    attn_mma<<<dim3(32, NH), 128, 65536>>>();

    /* 6. GEMM3: O @ Wo -> out */
    {
        GSegs g; g.n = 1;
        g.s[0] = { Oh, Ol, 2048, woh, wol, out, nullptr, nullptr, 2048, 2048, 0, 0 };
        g.s[1] = g.s[0]; g.s[2] = g.s[0]; g.s[3] = g.s[0];
        gemm_fused<<<dim3(16, 16), 256, 65536>>>(g);
    }
}

// round 7
// speedup vs baseline: 5.0075x; 1.0938x over previous
#include <cuda_runtime.h>
#include <cuda_bf16.h>
#include <math.h>
#include <stdint.h>

#define TSEQ   2048
#define DMODEL 2048
#define NH     16
#define DHEAD  128
#define DROPE  64
#define DCONT  64
#define SCALE_ATT 0.08838834764831845f  /* 1/sqrt(128) */

/* ------------------------------------------------------------------ */
/* Scratch (device globals)                                            */
/* ------------------------------------------------------------------ */
__device__ float g_qc[TSEQ * 1024];
__device__ float g_qr[TSEQ * 1024];
__device__ float g_kc[TSEQ * 1024];
__device__ float g_kr[TSEQ * 1024];
__device__ float g_cosT[TSEQ * 32];
__device__ float g_sinT[TSEQ * 32];

/* attention operands, bf16 hi/lo, [h][t][d] */
__device__ __nv_bfloat16 g_Qh[NH * TSEQ * DHEAD], g_Ql[NH * TSEQ * DHEAD];
__device__ __nv_bfloat16 g_Kh[NH * TSEQ * DHEAD], g_Kl[NH * TSEQ * DHEAD];
__device__ __nv_bfloat16 g_Vh[NH * TSEQ * DHEAD], g_Vl[NH * TSEQ * DHEAD];

/* bf16 hi/lo split operands for GEMMs */
__device__ __nv_bfloat16 g_xh[TSEQ * 2048],  g_xl[TSEQ * 2048];
__device__ __nv_bfloat16 g_qdh[TSEQ * 512],  g_qdl[TSEQ * 512];
__device__ __nv_bfloat16 g_kvh[TSEQ * 512],  g_kvl[TSEQ * 512];
__device__ __nv_bfloat16 g_Oh[TSEQ * 2048],  g_Ol[TSEQ * 2048];
__device__ __nv_bfloat16 g_wqdh[2048 * 512], g_wqdl[2048 * 512];
__device__ __nv_bfloat16 g_wquh[512 * 1024], g_wqul[512 * 1024];
__device__ __nv_bfloat16 g_wqrh[2048 * 1024],g_wqrl[2048 * 1024];
__device__ __nv_bfloat16 g_wkdh[2048 * 512], g_wkdl[2048 * 512];
__device__ __nv_bfloat16 g_wkuh[512 * 1024], g_wkul[512 * 1024];
__device__ __nv_bfloat16 g_wvuh[512 * 2048], g_wvul[512 * 2048];
__device__ __nv_bfloat16 g_wkrh[2048 * 1024],g_wkrl[2048 * 1024];
__device__ __nv_bfloat16 g_woh[2048 * 2048], g_wol[2048 * 2048];

/* ------------------------------------------------------------------ */
/* asm helpers                                                         */
/* ------------------------------------------------------------------ */
#define CPA16(dst, src)                                                    \
    asm volatile("cp.async.cg.shared.global [%0], [%1], 16;"               \
                 :: "r"(dst), "l"(src))
#define CPA_COMMIT() asm volatile("cp.async.commit_group;")
#define CPA_WAIT1()  asm volatile("cp.async.wait_group 1;")
#define CPA_WAIT0()  asm volatile("cp.async.wait_group 0;")

#define LDSM4(r0, r1, r2, r3, addr)                                        \
    asm volatile("ldmatrix.sync.aligned.m8n8.x4.shared.b16 {%0,%1,%2,%3}, [%4];" \
                 : "=r"(r0), "=r"(r1), "=r"(r2), "=r"(r3) : "r"(addr))
#define LDSM4T(r0, r1, r2, r3, addr)                                       \
    asm volatile("ldmatrix.sync.aligned.m8n8.x4.trans.shared.b16 {%0,%1,%2,%3}, [%4];" \
                 : "=r"(r0), "=r"(r1), "=r"(r2), "=r"(r3) : "r"(addr))
#define MMA_BF16(c, a, b0, b1)                                             \
    asm volatile("mma.sync.aligned.m16n8k16.row.col.f32.bf16.bf16.f32 "    \
                 "{%0,%1,%2,%3}, {%4,%5,%6,%7}, {%8,%9}, {%0,%1,%2,%3};"   \
                 : "+f"(c[0]), "+f"(c[1]), "+f"(c[2]), "+f"(c[3])          \
                 : "r"(a[0]), "r"(a[1]), "r"(a[2]), "r"(a[3]),             \
                   "r"(b0), "r"(b1))

__device__ __forceinline__ uint32_t bf2pack(float a, float b)
{
    return (uint32_t)__bfloat16_as_ushort(__float2bfloat16_rn(a)) |
           ((uint32_t)__bfloat16_as_ushort(__float2bfloat16_rn(b)) << 16);
}

/* ------------------------------------------------------------------ */
/* RoPE table                                                          */
/* ------------------------------------------------------------------ */
__global__ void __launch_bounds__(256) rope_table()
{
    const int idx = blockIdx.x * 256 + threadIdx.x;
    if (idx >= TSEQ * 32) return;
    const int t = idx >> 5, i = idx & 31;
    const double inv = pow(10000.0, -(double)i / 32.0);
    double sd, cd;
    sincos((double)t * inv, &sd, &cd);
    g_cosT[idx] = (float)cd;
    g_sinT[idx] = (float)sd;
}

/* ------------------------------------------------------------------ */
/* Batched fp32 -> bf16 hi/lo split                                    */
/* ------------------------------------------------------------------ */
struct SplitJob { const float* src; __nv_bfloat16 *h, *l; int n; };
struct SplitJobs { SplitJob j[9]; };

__global__ void __launch_bounds__(256) split_many(SplitJobs js)
{
    const SplitJob J = js.j[blockIdx.y];
    const int i = (blockIdx.x * 256 + threadIdx.x) << 2;
    if (i >= J.n) return;
    float4 v = *(const float4*)(J.src + i);
    float h0 = __bfloat162float(__float2bfloat16_rn(v.x));
    float h1 = __bfloat162float(__float2bfloat16_rn(v.y));
    float h2 = __bfloat162float(__float2bfloat16_rn(v.z));
    float h3 = __bfloat162float(__float2bfloat16_rn(v.w));
    uint2 hp, lp;
    hp.x = bf2pack(v.x, v.y);          hp.y = bf2pack(v.z, v.w);
    lp.x = bf2pack(v.x - h0, v.y - h1); lp.y = bf2pack(v.z - h2, v.w - h3);
    *(uint2*)(J.h + i) = hp;
    *(uint2*)(J.l + i) = lp;
}

/* ------------------------------------------------------------------ */
/* Fused multi-segment split-bf16 tensor-core GEMM.                    */
/* BM=BN=128, BK=64, 256 threads, 2-stage cp.async, 128KB smem.        */
/* ------------------------------------------------------------------ */
struct GSeg {
    const __nv_bfloat16 *Ah, *Al;
    int lda;
    const __nv_bfloat16 *Bh, *Bl;
    float* Cf;
    __nv_bfloat16 *Ch, *Cl;
    int N, K, tile0, vperm;
};
struct GSegs { GSeg s[4]; int n; };

#define G_STAGE 65536
#define GA_LO   16384
#define GB_HI   32768
#define GB_LO   49152

/* A tile: 128 rows x 8 chunks(16B) = 128x64 bf16 */
__device__ __forceinline__ uint32_t offA64(int r, int c)
{ return (uint32_t)(((r << 3) + (c ^ (r & 7))) << 4); }
/* B tile: 64 rows x 16 chunks(16B) = 64x128 bf16 */
__device__ __forceinline__ uint32_t offB(int r, int c)
{ return (uint32_t)(((r << 4) + (c ^ (r & 7))) << 4); }

__global__ void __launch_bounds__(256) gemm_fused(GSegs segs)
{
    extern __shared__ char dsm[];
    const uint32_t sb = (uint32_t)__cvta_generic_to_shared(dsm);

    const int tid  = threadIdx.x;
    const int lane = tid & 31;
    const int warp = tid >> 5;
    const int wm   = (warp >> 1) << 5;
    const int wn   = (warp & 1) << 6;
    const int bm   = blockIdx.y << 7;

    GSeg sg = segs.s[0];
#pragma unroll
    for (int i = 1; i < 4; i++)
        if (i < segs.n && (int)blockIdx.x >= segs.s[i].tile0) sg = segs.s[i];
    const int bn  = ((int)blockIdx.x - sg.tile0) << 7;
    const int lda = sg.lda, ldb = sg.N, K = sg.K;

    /* staging indices: A 32 rows/pass x 8 chunks; B 16 rows/pass x 16 chunks */
    const int ar = tid >> 3, ac = tid & 7;
    const int br = tid >> 4, bc = tid & 15;

    const __nv_bfloat16* gAh = sg.Ah + (size_t)(bm + ar) * lda + ac * 8;
    const __nv_bfloat16* gAl = sg.Al + (size_t)(bm + ar) * lda + ac * 8;
    const __nv_bfloat16* gBh = sg.Bh + (size_t)br * ldb + bn + bc * 8;
    const __nv_bfloat16* gBl = sg.Bl + (size_t)br * ldb + bn + bc * 8;

    float acc[2][8][4];
#pragma unroll
    for (int mt = 0; mt < 2; mt++)
#pragma unroll
        for (int nt = 0; nt < 8; nt++)
#pragma unroll
            for (int i = 0; i < 4; i++) acc[mt][nt][i] = 0.f;

    const int nk = K >> 6;

    auto load_stage = [&](int st, int k0) {
        const uint32_t s0 = sb + st * G_STAGE;
        const __nv_bfloat16* pAh = gAh + k0;
        const __nv_bfloat16* pAl = gAl + k0;
#pragma unroll
        for (int p = 0; p < 4; p++) {
            const uint32_t ao = offA64(ar + (p << 5), ac);
            CPA16(s0 + ao,         pAh + (size_t)(p << 5) * lda);
            CPA16(s0 + GA_LO + ao, pAl + (size_t)(p << 5) * lda);
        }
        const __nv_bfloat16* pBh = gBh + (size_t)k0 * ldb;
        const __nv_bfloat16* pBl = gBl + (size_t)k0 * ldb;
#pragma unroll
        for (int p = 0; p < 4; p++) {
            const uint32_t bo = offB(br + (p << 4), bc);
            CPA16(s0 + GB_HI + bo, pBh + (size_t)(p << 4) * ldb);
            CPA16(s0 + GB_LO + bo, pBl + (size_t)(p << 4) * ldb);
        }
    };

    load_stage(0, 0);
    CPA_COMMIT();

    for (int it = 0; it < nk; it++) {
        if (it + 1 < nk) { load_stage((it + 1) & 1, (it + 1) << 6); CPA_COMMIT(); }
        if (it + 1 < nk) CPA_WAIT1(); else CPA_WAIT0();
        __syncthreads();

        const uint32_t s0 = sb + (it & 1) * G_STAGE;
#pragma unroll
        for (int ks = 0; ks < 4; ks++) {
            uint32_t ah[2][4], al_[2][4];
#pragma unroll
            for (int mt = 0; mt < 2; mt++) {
                const int rowA   = wm + (mt << 4) + (lane & 15);
                const int chunkA = (ks << 1) + (lane >> 4);
                const uint32_t ad = s0 + offA64(rowA, chunkA);
                LDSM4(ah[mt][0], ah[mt][1], ah[mt][2], ah[mt][3], ad);
                LDSM4(al_[mt][0], al_[mt][1], al_[mt][2], al_[mt][3], ad + GA_LO);
            }
            uint32_t bhf[8][2], blf[8][2];
#pragma unroll
            for (int np = 0; np < 4; np++) {
                const int rowB   = (ks << 4) + (lane & 15);
                const int chunkB = (wn >> 3) + (lane >> 4) + (np << 1);
                const uint32_t bd = s0 + GB_HI + offB(rowB, chunkB);
                uint32_t r0, r1, r2, r3;
                LDSM4T(r0, r1, r2, r3, bd);
                bhf[2 * np][0] = r0; bhf[2 * np][1] = r1;
                bhf[2 * np + 1][0] = r2; bhf[2 * np + 1][1] = r3;
                LDSM4T(r0, r1, r2, r3, bd + 16384);
                blf[2 * np][0] = r0; blf[2 * np][1] = r1;
                blf[2 * np + 1][0] = r2; blf[2 * np + 1][1] = r3;
            }
#pragma unroll
            for (int mt = 0; mt < 2; mt++)
#pragma unroll
                for (int nt = 0; nt < 8; nt++) {
                    MMA_BF16(acc[mt][nt], ah[mt],  bhf[nt][0], bhf[nt][1]);
                    MMA_BF16(acc[mt][nt], ah[mt],  blf[nt][0], blf[nt][1]);
                    MMA_BF16(acc[mt][nt], al_[mt], bhf[nt][0], bhf[nt][1]);
                }
        }
        __syncthreads();
    }

    const int erow = lane >> 2;
    const int ecol = (lane & 3) << 1;
    if (sg.Cf) {
#pragma unroll
        for (int mt = 0; mt < 2; mt++)
#pragma unroll
            for (int nt = 0; nt < 8; nt++) {
                const int r = bm + wm + (mt << 4) + erow;
                const int c = bn + wn + (nt << 3) + ecol;
                *(float2*)(sg.Cf + (size_t)r * ldb + c) =
                    make_float2(acc[mt][nt][0], acc[mt][nt][1]);
                *(float2*)(sg.Cf + (size_t)(r + 8) * ldb + c) =
                    make_float2(acc[mt][nt][2], acc[mt][nt][3]);
            }
    } else {
#pragma unroll
        for (int mt = 0; mt < 2; mt++)
#pragma unroll
            for (int nt = 0; nt < 8; nt++) {
                const int r = bm + wm + (mt << 4) + erow;
                const int c = bn + wn + (nt << 3) + ecol;
#pragma unroll
                for (int hh = 0; hh < 2; hh++) {
                    const float v0 = acc[mt][nt][2 * hh];
                    const float v1 = acc[mt][nt][2 * hh + 1];
                    const float h0 = __bfloat162float(__float2bfloat16_rn(v0));
                    const float h1 = __bfloat162float(__float2bfloat16_rn(v1));
                    const int rr = r + 8 * hh;
                    size_t idx;
                    if (sg.vperm)
                        idx = ((size_t)(c >> 7) * TSEQ + rr) * DHEAD + (c & 127);
                    else
                        idx = (size_t)rr * ldb + c;
                    *(uint32_t*)(sg.Ch + idx) = bf2pack(v0, v1);
                    *(uint32_t*)(sg.Cl + idx) = bf2pack(v0 - h0, v1 - h1);
                }
            }
    }
}

/* ------------------------------------------------------------------ */
/* Pack + RoPE -> Qh/Ql (pre-scaled), Kh/Kl in [h][t][d].              */
/* ------------------------------------------------------------------ */
__global__ void __launch_bounds__(64) pack_kernel()
{
    const int t = blockIdx.x;
    const int h = blockIdx.y;
    const int d2 = threadIdx.x << 1;
    const size_t o = ((size_t)h * TSEQ + t) * DHEAD + d2;

    float q0, q1, k0, k1;
    if (d2 < DCONT) {
        const size_t b = (size_t)t * 1024 + h * DCONT + d2;
        q0 = g_qc[b];     q1 = g_qc[b + 1];
        k0 = g_kc[b];     k1 = g_kc[b + 1];
    } else {
        const int i = d2 - DCONT;
        const int ip = (i < 32) ? i : i - 32;
        const float c0 = g_cosT[t * 32 + ip],     s0 = g_sinT[t * 32 + ip];
        const float c1 = g_cosT[t * 32 + ip + 1], s1 = g_sinT[t * 32 + ip + 1];
        const size_t b = (size_t)t * 1024 + h * DROPE;
        const float qa0 = g_qr[b + ip],      qa1 = g_qr[b + ip + 1];
        const float qb0 = g_qr[b + 32 + ip], qb1 = g_qr[b + 32 + ip + 1];
        const float ka0 = g_kr[b + ip],      ka1 = g_kr[b + ip + 1];
        const float kb0 = g_kr[b + 32 + ip], kb1 = g_kr[b + 32 + ip + 1];
        if (i < 32) {
            q0 = qa0 * c0 - qb0 * s0;  q1 = qa1 * c1 - qb1 * s1;
            k0 = ka0 * c0 - kb0 * s0;  k1 = ka1 * c1 - kb1 * s1;
        } else {
            q0 = qa0 * s0 + qb0 * c0;  q1 = qa1 * s1 + qb1 * c1;
            k0 = ka0 * s0 + kb0 * c0;  k1 = ka1 * s1 + kb1 * c1;
        }
    }
    q0 *= SCALE_ATT; q1 *= SCALE_ATT;

    const float qh0 = __bfloat162float(__float2bfloat16_rn(q0));
    const float qh1 = __bfloat162float(__float2bfloat16_rn(q1));
    const float kh0 = __bfloat162float(__float2bfloat16_rn(k0));
    const float kh1 = __bfloat162float(__float2bfloat16_rn(k1));
    *(uint32_t*)(g_Qh + o) = bf2pack(q0, q1);
    *(uint32_t*)(g_Ql + o) = bf2pack(q0 - qh0, q1 - qh1);
    *(uint32_t*)(g_Kh + o) = bf2pack(k0, k1);
    *(uint32_t*)(g_Kl + o) = bf2pack(k0 - kh0, k1 - kh1);
}

/* ------------------------------------------------------------------ */
/* Tensor-core causal flash attention (split bf16).                    */
/* K and V in separate commit groups: V load hidden under QK^T.        */
/* ------------------------------------------------------------------ */
__device__ __forceinline__ uint32_t offV(int r, int c)
{ return (uint32_t)(((r << 4) + (c ^ (r & 7))) << 4); }   /* 16 chunks/row */

#define SM_KH 0
#define SM_KL 16384
#define SM_VH 32768
#define SM_VL 49152

__global__ void __launch_bounds__(128) attn_mma()
{
    extern __shared__ char dsm[];
    const uint32_t sb = (uint32_t)__cvta_generic_to_shared(dsm);

    const int h    = blockIdx.y;
    const int qblk = 31 - (int)blockIdx.x;       /* long CTAs first */
    const int qb   = qblk << 6;
    const int tid  = threadIdx.x;
    const int lane = tid & 31;
    const int warp = tid >> 5;
    const int w16  = warp << 4;

    const __nv_bfloat16* Qhb = g_Qh + (size_t)h * TSEQ * DHEAD;
    const __nv_bfloat16* Qlb = g_Ql + (size_t)h * TSEQ * DHEAD;
    const __nv_bfloat16* Khb = g_Kh + (size_t)h * TSEQ * DHEAD;
    const __nv_bfloat16* Klb = g_Kl + (size_t)h * TSEQ * DHEAD;
    const __nv_bfloat16* Vhb = g_Vh + (size_t)h * TSEQ * DHEAD;
    const __nv_bfloat16* Vlb = g_Vl + (size_t)h * TSEQ * DHEAD;

    const int sr = tid >> 4;            /* 0..7  */
    const int sc = tid & 15;            /* 0..15 */

    /* ---- stage Q (64 rows), LDSM into regs ---- */
#pragma unroll
    for (int p = 0; p < 8; p++) {
        const int r = sr + (p << 3);
        CPA16(sb + SM_KH + offV(r, sc), Qhb + (size_t)(qb + r) * DHEAD + sc * 8);
        CPA16(sb + SM_KL + offV(r, sc), Qlb + (size_t)(qb + r) * DHEAD + sc * 8);
    }
    CPA_COMMIT(); CPA_WAIT0();
    __syncthreads();

    uint32_t qh[8][4], ql[8][4];
#pragma unroll
    for (int ks = 0; ks < 8; ks++) {
        const uint32_t ad = offV(w16 + (lane & 15), (ks << 1) + (lane >> 4));
        LDSM4(qh[ks][0], qh[ks][1], qh[ks][2], qh[ks][3], sb + SM_KH + ad);
        LDSM4(ql[ks][0], ql[ks][1], ql[ks][2], ql[ks][3], sb + SM_KL + ad);
    }
    __syncthreads();

    float O[16][4];
#pragma unroll
    for (int nt = 0; nt < 16; nt++)
#pragma unroll
        for (int i = 0; i < 4; i++) O[nt][i] = 0.f;
    float m0 = -1e30f, m1 = -1e30f, l0 = 0.f, l1 = 0.f;

    const int ntiles = qblk + 1;
    const int row0 = qb + w16 + (lane >> 2);
    const int row1 = row0 + 8;

    for (int kt = 0; kt < ntiles; kt++) {
        const int kb = kt << 6;

        /* stage K (group A), then V (group B) */
#pragma unroll
        for (int p = 0; p < 8; p++) {
            const int r = sr + (p << 3);
            const size_t gi = (size_t)(kb + r) * DHEAD + sc * 8;
            const uint32_t so = offV(r, sc);
            CPA16(sb + SM_KH + so, Khb + gi);
            CPA16(sb + SM_KL + so, Klb + gi);
        }
        CPA_COMMIT();
#pragma unroll
        for (int p = 0; p < 8; p++) {
            const int r = sr + (p << 3);
            const size_t gi = (size_t)(kb + r) * DHEAD + sc * 8;
            const uint32_t so = offV(r, sc);
            CPA16(sb + SM_VH + so, Vhb + gi);
            CPA16(sb + SM_VL + so, Vlb + gi);
        }
        CPA_COMMIT();
        CPA_WAIT1();                      /* K ready; V still in flight */
        __syncthreads();

        /* ---- scores S = Q K^T ---- */
        float S[8][4];
#pragma unroll
        for (int nt = 0; nt < 8; nt++)
#pragma unroll
            for (int i = 0; i < 4; i++) S[nt][i] = 0.f;

#pragma unroll
        for (int ntp = 0; ntp < 4; ntp++) {
#pragma unroll
            for (int ks = 0; ks < 8; ks++) {
                const uint32_t ad = offV((ntp << 4) + (lane & 15),
                                         (ks << 1) + (lane >> 4));
                uint32_t kh0, kh1, kh2, kh3, kl0, kl1, kl2, kl3;
                LDSM4(kh0, kh1, kh2, kh3, sb + SM_KH + ad);
                LDSM4(kl0, kl1, kl2, kl3, sb + SM_KL + ad);
                MMA_BF16(S[2 * ntp],     qh[ks], kh0, kh2);
                MMA_BF16(S[2 * ntp],     qh[ks], kl0, kl2);
                MMA_BF16(S[2 * ntp],     ql[ks], kh0, kh2);
                MMA_BF16(S[2 * ntp + 1], qh[ks], kh1, kh3);
                MMA_BF16(S[2 * ntp + 1], qh[ks], kl1, kl3);
                MMA_BF16(S[2 * ntp + 1], ql[ks], kh1, kh3);
            }
        }

        /* ---- causal mask on diagonal tile ---- */
        if (kb == qb) {
#pragma unroll
            for (int nt = 0; nt < 8; nt++) {
                const int key = kb + (nt << 3) + ((lane & 3) << 1);
                if (key > row0)     S[nt][0] = -1e30f;
                if (key + 1 > row0) S[nt][1] = -1e30f;
                if (key > row1)     S[nt][2] = -1e30f;
                if (key + 1 > row1) S[nt][3] = -1e30f;
            }
        }

        /* ---- online softmax ---- */
        float mx0 = -1e30f, mx1 = -1e30f;
#pragma unroll
        for (int nt = 0; nt < 8; nt++) {
            mx0 = fmaxf(mx0, fmaxf(S[nt][0], S[nt][1]));
            mx1 = fmaxf(mx1, fmaxf(S[nt][2], S[nt][3]));
        }
        mx0 = fmaxf(mx0, __shfl_xor_sync(0xffffffffu, mx0, 1));
        mx0 = fmaxf(mx0, __shfl_xor_sync(0xffffffffu, mx0, 2));
        mx1 = fmaxf(mx1, __shfl_xor_sync(0xffffffffu, mx1, 1));
        mx1 = fmaxf(mx1, __shfl_xor_sync(0xffffffffu, mx1, 2));

        const float m0n = fmaxf(m0, mx0), m1n = fmaxf(m1, mx1);
        const float a0 = __expf(m0 - m0n), a1 = __expf(m1 - m1n);
        m0 = m0n; m1 = m1n;

        uint32_t aH[4][4], aL[4][4];
        float ps0 = 0.f, ps1 = 0.f;
#pragma unroll
        for (int nt = 0; nt < 8; nt++) {
            const float p0 = __expf(S[nt][0] - m0n);
            const float p1 = __expf(S[nt][1] - m0n);
            const float p2 = __expf(S[nt][2] - m1n);
            const float p3 = __expf(S[nt][3] - m1n);
            ps0 += p0 + p1; ps1 += p2 + p3;
            const float h0 = __bfloat162float(__float2bfloat16_rn(p0));
            const float h1 = __bfloat162float(__float2bfloat16_rn(p1));
            const float h2 = __bfloat162float(__float2bfloat16_rn(p2));
            const float h3 = __bfloat162float(__float2bfloat16_rn(p3));
            const int kk = nt >> 1;
            const int e  = (nt & 1) << 1;
            aH[kk][e]     = bf2pack(p0, p1);
            aH[kk][e + 1] = bf2pack(p2, p3);
            aL[kk][e]     = bf2pack(p0 - h0, p1 - h1);
            aL[kk][e + 1] = bf2pack(p2 - h2, p3 - h3);
        }
        ps0 += __shfl_xor_sync(0xffffffffu, ps0, 1);
        ps0 += __shfl_xor_sync(0xffffffffu, ps0, 2);
        ps1 += __shfl_xor_sync(0xffffffffu, ps1, 1);
        ps1 += __shfl_xor_sync(0xffffffffu, ps1, 2);
        l0 = l0 * a0 + ps0;
        l1 = l1 * a1 + ps1;

#pragma unroll
        for (int nt = 0; nt < 16; nt++) {
            O[nt][0] *= a0; O[nt][1] *= a0;
            O[nt][2] *= a1; O[nt][3] *= a1;
        }

        CPA_WAIT0();                      /* V ready */
        __syncthreads();

        /* ---- O += P V ---- */
#pragma unroll
        for (int kk = 0; kk < 4; kk++) {
#pragma unroll
            for (int ntp = 0; ntp < 8; ntp++) {
                const uint32_t ad = offV((kk << 4) + (lane & 15),
                                         (ntp << 1) + (lane >> 4));
                uint32_t vh0, vh1, vh2, vh3, vl0, vl1, vl2, vl3;
                LDSM4T(vh0, vh1, vh2, vh3, sb + SM_VH + ad);
                LDSM4T(vl0, vl1, vl2, vl3, sb + SM_VL + ad);
                MMA_BF16(O[2 * ntp],     aH[kk], vh0, vh1);
                MMA_BF16(O[2 * ntp],     aH[kk], vl0, vl1);
                MMA_BF16(O[2 * ntp],     aL[kk], vh0, vh1);
                MMA_BF16(O[2 * ntp + 1], aH[kk], vh2, vh3);
                MMA_BF16(O[2 * ntp + 1], aH[kk], vl2, vl3);
                MMA_BF16(O[2 * ntp + 1], aL[kk], vh2, vh3);
            }
        }
        __syncthreads();
    }

    /* ---- epilogue ---- */
    const float inv0 = 1.0f / l0, inv1 = 1.0f / l1;
#pragma unroll
    for (int nt = 0; nt < 16; nt++) {
        const int d = (nt << 3) + ((lane & 3) << 1);
        const float v0 = O[nt][0] * inv0, v1 = O[nt][1] * inv0;
        const float v2 = O[nt][2] * inv1, v3 = O[nt][3] * inv1;
        const float h0 = __bfloat162float(__float2bfloat16_rn(v0));
        const float h1 = __bfloat162float(__float2bfloat16_rn(v1));
        const float h2 = __bfloat162float(__float2bfloat16_rn(v2));
        const float h3 = __bfloat162float(__float2bfloat16_rn(v3));
        const size_t i0 = (size_t)row0 * DMODEL + h * DHEAD + d;
        const size_t i1 = (size_t)row1 * DMODEL + h * DHEAD + d;
        *(uint32_t*)(g_Oh + i0) = bf2pack(v0, v1);
        *(uint32_t*)(g_Ol + i0) = bf2pack(v0 - h0, v1 - h1);
        *(uint32_t*)(g_Oh + i1) = bf2pack(v2, v3);
        *(uint32_t*)(g_Ol + i1) = bf2pack(v2 - h2, v3 - h3);
    }
}

/* ------------------------------------------------------------------ */
extern "C" void kernel_launch(void* const* d_in, const int* in_sizes, int n_in,
                              void* d_out, int out_size)
{
    const float* x        = (const float*)d_in[0];
    const float* Wq_down  = (const float*)d_in[1];
    const float* Wq_up    = (const float*)d_in[2];
    const float* Wq_rope  = (const float*)d_in[3];
    const float* Wkv_down = (const float*)d_in[4];
    const float* Wk_up    = (const float*)d_in[5];
    const float* Wv_up    = (const float*)d_in[6];
    const float* Wk_rope  = (const float*)d_in[7];
    const float* Wo       = (const float*)d_in[8];
    float* out = (float*)d_out;

    float *qc, *qr, *kc, *kr;
    cudaGetSymbolAddress((void**)&qc, g_qc);
    cudaGetSymbolAddress((void**)&qr, g_qr);
    cudaGetSymbolAddress((void**)&kc, g_kc);
    cudaGetSymbolAddress((void**)&kr, g_kr);

    __nv_bfloat16 *xh, *xl, *qdh, *qdl, *kvh, *kvl, *Oh, *Ol, *Vh, *Vl;
    __nv_bfloat16 *wqdh, *wqdl, *wquh, *wqul, *wqrh, *wqrl, *wkdh, *wkdl;
    __nv_bfloat16 *wkuh, *wkul, *wvuh, *wvul, *wkrh, *wkrl, *woh, *wol;
    cudaGetSymbolAddress((void**)&xh, g_xh);   cudaGetSymbolAddress((void**)&xl, g_xl);
    cudaGetSymbolAddress((void**)&qdh, g_qdh); cudaGetSymbolAddress((void**)&qdl, g_qdl);
    cudaGetSymbolAddress((void**)&kvh, g_kvh); cudaGetSymbolAddress((void**)&kvl, g_kvl);
    cudaGetSymbolAddress((void**)&Oh, g_Oh);   cudaGetSymbolAddress((void**)&Ol, g_Ol);
    cudaGetSymbolAddress((void**)&Vh, g_Vh);   cudaGetSymbolAddress((void**)&Vl, g_Vl);
    cudaGetSymbolAddress((void**)&wqdh, g_wqdh); cudaGetSymbolAddress((void**)&wqdl, g_wqdl);
    cudaGetSymbolAddress((void**)&wquh, g_wquh); cudaGetSymbolAddress((void**)&wqul, g_wqul);
    cudaGetSymbolAddress((void**)&wqrh, g_wqrh); cudaGetSymbolAddress((void**)&wqrl, g_wqrl);
    cudaGetSymbolAddress((void**)&wkdh, g_wkdh); cudaGetSymbolAddress((void**)&wkdl, g_wkdl);
    cudaGetSymbolAddress((void**)&wkuh, g_wkuh); cudaGetSymbolAddress((void**)&wkul, g_wkul);
    cudaGetSymbolAddress((void**)&wvuh, g_wvuh); cudaGetSymbolAddress((void**)&wvul, g_wvul);
    cudaGetSymbolAddress((void**)&wkrh, g_wkrh); cudaGetSymbolAddress((void**)&wkrl, g_wkrl);
    cudaGetSymbolAddress((void**)&woh, g_woh);   cudaGetSymbolAddress((void**)&wol, g_wol);

    cudaFuncSetAttribute(gemm_fused,
                         cudaFuncAttributeMaxDynamicSharedMemorySize, 131072);
    cudaFuncSetAttribute(attn_mma,
                         cudaFuncAttributeMaxDynamicSharedMemorySize, 65536);

    /* 0. rope table */
    rope_table<<<256, 256>>>();

    /* 1. split inputs + weights */
    SplitJobs js;
    js.j[0] = { x,        xh,   xl,   TSEQ * 2048 };
    js.j[1] = { Wq_down,  wqdh, wqdl, 2048 * 512  };
    js.j[2] = { Wq_up,    wquh, wqul, 512 * 1024  };
    js.j[3] = { Wq_rope,  wqrh, wqrl, 2048 * 1024 };
    js.j[4] = { Wkv_down, wkdh, wkdl, 2048 * 512  };
    js.j[5] = { Wk_up,    wkuh, wkul, 512 * 1024  };
    js.j[6] = { Wv_up,    wvuh, wvul, 512 * 2048  };
    js.j[7] = { Wk_rope,  wkrh, wkrl, 2048 * 1024 };
    js.j[8] = { Wo,       woh,  wol,  2048 * 2048 };
    split_many<<<dim3(4096, 9), 256>>>(js);

    /* 2. GEMM1: x @ [Wq_down | Wkv_down | Wq_rope | Wk_rope] */
    {
        GSegs g; g.n = 4;
        g.s[0] = { xh, xl, 2048, wqdh, wqdl, nullptr, qdh, qdl,  512, 2048, 0,  0 };
        g.s[1] = { xh, xl, 2048, wkdh, wkdl, nullptr, kvh, kvl,  512, 2048, 4,  0 };
        g.s[2] = { xh, xl, 2048, wqrh, wqrl, qr, nullptr, nullptr, 1024, 2048, 8,  0 };
        g.s[3] = { xh, xl, 2048, wkrh, wkrl, kr, nullptr, nullptr, 1024, 2048, 16, 0 };
        gemm_fused<<<dim3(24, 16), 256, 131072>>>(g);
    }

    /* 3. GEMM2: qd @ Wq_up ; kv @ [Wk_up | Wv_up (-> Vh/Vl permuted)] */
    {
        GSegs g; g.n = 3;
        g.s[0] = { qdh, qdl, 512, wquh, wqul, qc, nullptr, nullptr, 1024, 512, 0,  0 };
        g.s[1] = { kvh, kvl, 512, wkuh, wkul, kc, nullptr, nullptr, 1024, 512, 8,  0 };
        g.s[2] = { kvh, kvl, 512, wvuh, wvul, nullptr, Vh, Vl,      2048, 512, 16, 1 };
        g.s[3] = g.s[0];
        gemm_fused<<<dim3(32, 16), 256, 131072>>>(g);
    }

    /* 4. rope + pack Q/K */
    pack_kernel<<<dim3(TSEQ, NH), 64>>>();

    /* 5. tensor-core causal attention */
    attn_mma<<<dim3(32, NH), 128, 65536>>>();

    /* 6. GEMM3: O @ Wo -> out */
    {
        GSegs g; g.n = 1;
        g.s[0] = { Oh, Ol, 2048, woh, wol, out, nullptr, nullptr, 2048, 2048, 0, 0 };
        g.s[1] = g.s[0]; g.s[2] = g.s[0]; g.s[3] = g.s[0];
        gemm_fused<<<dim3(16, 16), 256, 131072>>>(g);
    }
}